// round 12
// baseline (speedup 1.0000x reference)
#include <cuda_runtime.h>
#include <cuda_bf16.h>
#include <cstdint>
#include <math.h>

// Problem constants
#define DIMC   384
#define HEADS  8
#define CPH    48
#define HH     256
#define WW     256
#define HW     65536
#define BATCH  2
#define QKV_M  1152        // 3*dim

// ---------------- scratch (device globals) ----------------------------------
__device__ float g_qkv[(size_t)BATCH * QKV_M * HW];           // [b][1152][hw] f32
__device__ float g_win[(size_t)BATCH * HEADS * 1024 * 144 * 64]; // window-major dwconv out
__device__ __nv_bfloat16 g_xt_hi[(size_t)BATCH * HW * DIMC];  // [b][hw][384]
__device__ __nv_bfloat16 g_xt_lo[(size_t)BATCH * HW * DIMC];
__device__ __nv_bfloat16 g_at_hi[(size_t)BATCH * HW * DIMC];
__device__ __nv_bfloat16 g_at_lo[(size_t)BATCH * HW * DIMC];
__device__ __nv_bfloat16 g_wq_hi[QKV_M * DIMC], g_wq_lo[QKV_M * DIMC];
__device__ __nv_bfloat16 g_wp_hi[DIMC * DIMC],  g_wp_lo[DIMC * DIMC];

// ---------------- helpers ----------------------------------------------------
__device__ __forceinline__ uint32_t smem_u32(const void* p) {
    uint32_t a;
    asm("{ .reg .u64 t; cvta.to.shared.u64 t, %1; cvt.u32.u64 %0, t; }" : "=r"(a) : "l"(p));
    return a;
}
#define CP_ASYNC16(saddr, gptr) \
    asm volatile("cp.async.cg.shared.global [%0], [%1], 16;" :: "r"(saddr), "l"(gptr))
#define CP_COMMIT() asm volatile("cp.async.commit_group;" ::: "memory")
#define CP_WAIT0()  asm volatile("cp.async.wait_group 0;" ::: "memory")
#define CP_WAIT1()  asm volatile("cp.async.wait_group 1;" ::: "memory")

#define MBARRIER_INIT(addr, cnt) \
    asm volatile("mbarrier.init.shared.b64 [%0], %1;" :: "r"((uint32_t)(addr)), "r"((uint32_t)(cnt)) : "memory")
#define MBARRIER_EXPECT_TX(addr, bytes) \
    asm volatile("mbarrier.arrive.expect_tx.shared.b64 _, [%0], %1;" :: "r"((uint32_t)(addr)), "r"((uint32_t)(bytes)) : "memory")
#define MBARRIER_WAIT_PARITY(mbar_addr, parity) do { \
    uint32_t _mbar = (uint32_t)(mbar_addr); \
    uint32_t _par = (uint32_t)(parity); \
    uint32_t _done; \
    asm volatile( \
        "{\n\t.reg .pred p;\n\t" \
        "mbarrier.try_wait.parity.shared.b64 p, [%1], %2;\n\t" \
        "selp.b32 %0, 1, 0, p;\n\t}" \
        : "=r"(_done) : "r"(_mbar), "r"(_par) : "memory"); \
    if (!_done) { \
        asm volatile( \
            "{\n\t.reg .pred P1;\n\t" \
            "WL_%=:\n\t" \
            "mbarrier.try_wait.parity.shared.b64 P1, [%0], %1;\n\t" \
            "@P1 bra.uni WD_%=;\n\t" \
            "bra.uni WL_%=;\n\t" \
            "WD_%=:\n\t}" \
            :: "r"(_mbar), "r"(_par) : "memory"); \
    } \
} while (0)
#define BULK_CPY(dst_smem, gsrc, bytes, mbar) \
    asm volatile("cp.async.bulk.shared::cta.global.mbarrier::complete_tx::bytes [%0], [%1], %2, [%3];" \
                 :: "r"((uint32_t)(dst_smem)), "l"(gsrc), "r"((uint32_t)(bytes)), "r"((uint32_t)(mbar)) : "memory")
#define FENCE_PROXY_ASYNC() asm volatile("fence.proxy.async.shared::cta;" ::: "memory")

__device__ __forceinline__ void ldmx4(uint32_t* d, uint32_t addr) {
    asm volatile("ldmatrix.sync.aligned.m8n8.x4.shared.b16 {%0,%1,%2,%3}, [%4];"
                 : "=r"(d[0]), "=r"(d[1]), "=r"(d[2]), "=r"(d[3]) : "r"(addr));
}
__device__ __forceinline__ void ldmx2(uint32_t* d, uint32_t addr) {
    asm volatile("ldmatrix.sync.aligned.m8n8.x2.shared.b16 {%0,%1}, [%2];"
                 : "=r"(d[0]), "=r"(d[1]) : "r"(addr));
}
__device__ __forceinline__ void mma16816(float* c, const uint32_t* a, uint32_t b0, uint32_t b1) {
    asm volatile("mma.sync.aligned.m16n8k16.row.col.f32.bf16.bf16.f32 "
                 "{%0,%1,%2,%3}, {%4,%5,%6,%7}, {%8,%9}, {%0,%1,%2,%3};"
                 : "+f"(c[0]), "+f"(c[1]), "+f"(c[2]), "+f"(c[3])
                 : "r"(a[0]), "r"(a[1]), "r"(a[2]), "r"(a[3]), "r"(b0), "r"(b1));
}
__device__ __forceinline__ uint32_t swz(int r, int cb) {          // 64B rows (GEMM tiles)
    return (uint32_t)(r * 64 + ((cb ^ ((r >> 1) & 3)) << 4));
}
__device__ __forceinline__ uint32_t swz128r(int r, int cb) {      // 128B rows (attn bf16)
    return (uint32_t)(r * 128 + ((cb ^ (r & 7)) << 4));
}

// ---------------- transpose + hi/lo bf16 split (for x only) ------------------
__global__ __launch_bounds__(256) void transpose_split(
    const float* __restrict__ in, __nv_bfloat16* __restrict__ hi,
    __nv_bfloat16* __restrict__ lo, int C, int N)
{
    __shared__ float t[32][33];
    const int n0 = blockIdx.x * 32, c0 = blockIdx.y * 32;
    const size_t base = (size_t)blockIdx.z * C * N;
    const int tx = threadIdx.x & 31, ty = threadIdx.x >> 5;
#pragma unroll
    for (int i = 0; i < 4; i++) {
        const int c = ty + i * 8;
        t[c][tx] = in[base + (size_t)(c0 + c) * N + n0 + tx];
    }
    __syncthreads();
#pragma unroll
    for (int i = 0; i < 4; i++) {
        const int n = ty + i * 8;
        const float v = t[tx][n];
        const __nv_bfloat16 h = __float2bfloat16(v);
        const size_t o = base + (size_t)(n0 + n) * C + c0 + tx;
        hi[o] = h;
        lo[o] = __float2bfloat16(v - __bfloat162float(h));
    }
}

__global__ void split_w(const float* __restrict__ w, __nv_bfloat16* __restrict__ hi,
                        __nv_bfloat16* __restrict__ lo, int n)
{
    const int i = blockIdx.x * 256 + threadIdx.x;
    if (i < n) {
        const float v = w[i];
        const __nv_bfloat16 h = __float2bfloat16(v);
        hi[i] = h;
        lo[i] = __float2bfloat16(v - __bfloat162float(h));
    }
}

// ---------------- HMMA GEMM: C[M,N] = A[M,K] . B[N,K]^T ---------------------
// CTA tile 128(M) x 256(N), warp tile 64x64, K-stage 32, 3-stage cp.async ring.
// stage layout: Ah @0 (8K), Al @8K, Bh @16K (16K), Bl @32K; stage stride 48K.
#define HG_SMEM 147456

template <int WITH_BIAS>
__global__ __launch_bounds__(256, 1) void hmma_gemm(
    const __nv_bfloat16* __restrict__ Ahi, const __nv_bfloat16* __restrict__ Alo,
    const __nv_bfloat16* __restrict__ Bhi, const __nv_bfloat16* __restrict__ Blo,
    float* __restrict__ Cg, int M, int N, int K, const float* __restrict__ bias)
{
    extern __shared__ char smem[];
    const uint32_t sb = smem_u32(smem);
    const int tid = threadIdx.x;
    const int wid = tid >> 5, lane = tid & 31;
    const int bM = blockIdx.x * 128;
    const int bN = blockIdx.y * 256;
    const size_t bb = (size_t)blockIdx.z * (size_t)N * K;
    float* Cp = Cg + (size_t)blockIdx.z * (size_t)M * N;

    const __nv_bfloat16* Ah = Ahi + (size_t)bM * K;
    const __nv_bfloat16* Al = Alo + (size_t)bM * K;
    const __nv_bfloat16* Bh = Bhi + bb + (size_t)bN * K;
    const __nv_bfloat16* Bl = Blo + bb + (size_t)bN * K;

    const int cb = tid & 3;
    const int r0 = tid >> 2;      // 0..63
    const int nst = K / 32;       // 12

    // ---- prologue: fill stages 0,1 ----
#pragma unroll
    for (int ps = 0; ps < 2; ps++) {
        const uint32_t st = sb + ps * 49152;
        const int kk = ps * 32 + cb * 8;
#pragma unroll
        for (int i = 0; i < 2; i++) {
            const int r = r0 + i * 64;
            const uint32_t so = swz(r, cb);
            CP_ASYNC16(st + so,        Ah + (size_t)r * K + kk);
            CP_ASYNC16(st + 8192 + so, Al + (size_t)r * K + kk);
        }
#pragma unroll
        for (int i = 0; i < 4; i++) {
            const int r = r0 + i * 64;
            const uint32_t so = swz(r, cb);
            CP_ASYNC16(st + 16384 + so, Bh + (size_t)r * K + kk);
            CP_ASYNC16(st + 32768 + so, Bl + (size_t)r * K + kk);
        }
        CP_COMMIT();
    }

    float acc[4][8][4];
#pragma unroll
    for (int i = 0; i < 4; i++)
#pragma unroll
        for (int j = 0; j < 8; j++)
#pragma unroll
            for (int k = 0; k < 4; k++) acc[i][j][k] = 0.f;

    // warp tiling: 2(M) x 4(N); warp tile 64x64
    const int wm = (wid >> 2) * 64;
    const int wn = (wid & 3) * 64;
    const int a_rbase = wm + ((lane >> 3) & 1) * 8 + (lane & 7);
    const int a_cbad  = lane >> 4;
    const int b_rbase = wn + ((lane >> 4) & 1) * 8 + (lane & 7);
    const int b_cbad  = (lane >> 3) & 1;

    int sidx = 0;
    for (int s = 0; s < nst; s++) {
        if (s + 1 < nst) CP_WAIT1(); else CP_WAIT0();
        __syncthreads();

        // issue next stage's loads before compute
        if (s + 2 < nst) {
            int fi = sidx + 2; if (fi >= 3) fi -= 3;
            const uint32_t st = sb + fi * 49152;
            const int kk = (s + 2) * 32 + cb * 8;
#pragma unroll
            for (int i = 0; i < 2; i++) {
                const int r = r0 + i * 64;
                const uint32_t so = swz(r, cb);
                CP_ASYNC16(st + so,        Ah + (size_t)r * K + kk);
                CP_ASYNC16(st + 8192 + so, Al + (size_t)r * K + kk);
            }
#pragma unroll
            for (int i = 0; i < 4; i++) {
                const int r = r0 + i * 64;
                const uint32_t so = swz(r, cb);
                CP_ASYNC16(st + 16384 + so, Bh + (size_t)r * K + kk);
                CP_ASYNC16(st + 32768 + so, Bl + (size_t)r * K + kk);
            }
            CP_COMMIT();
        }

        const uint32_t st = sb + sidx * 49152;
#pragma unroll
        for (int k16 = 0; k16 < 2; k16++) {
            uint32_t bhf[4][4], blf[4][4];
#pragma unroll
            for (int nh = 0; nh < 4; nh++) {
                const uint32_t ad = st + 16384 + swz(b_rbase + nh * 16, k16 * 2 + b_cbad);
                ldmx4(bhf[nh], ad);
                ldmx4(blf[nh], ad + 16384);
            }
#pragma unroll
            for (int mh = 0; mh < 4; mh++) {
                uint32_t ahf[4], alf[4];
                const uint32_t ad = st + swz(a_rbase + mh * 16, k16 * 2 + a_cbad);
                ldmx4(ahf, ad);
                ldmx4(alf, ad + 8192);
#pragma unroll
                for (int nb = 0; nb < 8; nb++) {
                    const uint32_t* fh = &bhf[nb >> 1][(nb & 1) * 2];
                    const uint32_t* fl = &blf[nb >> 1][(nb & 1) * 2];
                    mma16816(acc[mh][nb], ahf, fh[0], fh[1]);
                    mma16816(acc[mh][nb], ahf, fl[0], fl[1]);
                    mma16816(acc[mh][nb], alf, fh[0], fh[1]);
                }
            }
        }
        if (++sidx == 3) sidx = 0;
    }
    __syncthreads();

    // ---- epilogue ----
    const int row0 = bM + wm + (lane >> 2);
    const int col0 = bN + wn + (lane & 3) * 2;
#pragma unroll
    for (int mh = 0; mh < 4; mh++) {
#pragma unroll
        for (int p = 0; p < 2; p++) {
            const int row = row0 + mh * 16 + p * 8;
            const float bi = WITH_BIAS ? __ldg(&bias[row]) : 0.f;
#pragma unroll
            for (int nb = 0; nb < 8; nb++) {
                float2 v;
                v.x = acc[mh][nb][p * 2 + 0] + bi;
                v.y = acc[mh][nb][p * 2 + 1] + bi;
                *reinterpret_cast<float2*>(&Cp[(size_t)row * N + col0 + nb * 8]) = v;
            }
        }
    }
}

// ---------------- dwconv 3x3 -> window-major (2 channels per stage) ----------
#define HSTR 40

__global__ __launch_bounds__(256) void dwconv_kernel(
    const float* __restrict__ qkv1,     // [b][1152][hw]
    const float* __restrict__ dww,      // [1152][9]
    float* __restrict__ gwin)
{
    __shared__ __align__(16) float h6[6][34 * HSTR];
    __shared__ float s_dww[144 * 9];
    __shared__ __align__(8) uint64_t mbar[3];

    const int tid  = threadIdx.x;
    const int tile = blockIdx.x;           // 0..63
    const int head = blockIdx.y;
    const int b    = blockIdx.z;
    const int tyb = tile >> 3, txb = tile & 7;
    const int y0 = tyb * 32 - 1, x0 = txb * 32 - 1;

    const int cs = x0 - 3;
    const int src_off = cs < 0 ? 0 : cs;
    const int dst_off = src_off - cs;
    const int cend = (cs + 40 > 256) ? 256 : (cs + 40);
    const uint32_t rowbytes = (uint32_t)(cend - src_off) * 4;
    const int r_lo = (y0 < 0) ? 1 : 0;
    const int r_hi = (y0 + 33 > 255) ? 32 : 33;
    const uint32_t expect2 = 2u * (uint32_t)(r_hi - r_lo + 1) * rowbytes;

    for (int e = tid; e < 144 * 9; e += 256) {
        const int l = e / 9, kk = e - l * 9;
        const int z = l / 48, cl = l - z * 48;
        s_dww[e] = dww[(size_t)(z * DIMC + head * CPH + cl) * 9 + kk];
    }
    for (int e = tid; e < 6 * 34 * HSTR; e += 256) (&h6[0][0])[e] = 0.f;
    if (tid < 3) MBARRIER_INIT(smem_u32(&mbar[tid]), 1);
    __syncthreads();
    FENCE_PROXY_ASYNC();

    const size_t bbase = (size_t)b * QKV_M * HW;
    const int wid = tid >> 5, lane = tid & 31;

    auto issue = [&](int s) {
        const int slot = s % 3;
        const uint32_t mb = smem_u32(&mbar[slot]);
        if (lane == 0) MBARRIER_EXPECT_TX(mb, expect2);
        for (int i = lane; i < 68; i += 32) {
            const int sub = i / 34;
            const int r = i - sub * 34;
            if (r < r_lo || r > r_hi) continue;
            const int ch = 2 * s + sub;
            const int gc = (ch / 48) * DIMC + head * CPH + (ch % 48);
            const float* srcc = qkv1 + bbase + (size_t)gc * HW;
            BULK_CPY(smem_u32(&h6[slot * 2 + sub][0]) + (uint32_t)(r * HSTR + dst_off) * 4,
                     srcc + (size_t)(y0 + r) * 256 + src_off, rowbytes, mb);
        }
    };
    if (wid == 0) { issue(0); issue(1); }

    const int orow = tid >> 3;
    const int xq   = (tid & 7) * 4;
    const int wy_l = orow >> 3, wx_l = xq >> 3;
    const int win = (tyb * 4 + wy_l) * 32 + txb * 4 + wx_l;
    float* wbase = gwin + (((size_t)(b * HEADS + head) * 1024 + win) * 144) * 64
                 + (orow & 7) * 8 + (xq & 7);

#pragma unroll 1
    for (int s = 0; s < 72; s++) {
        if (wid == 0 && s + 2 < 72) issue(s + 2);
        MBARRIER_WAIT_PARITY(smem_u32(&mbar[s % 3]), (s / 3) & 1);

#pragma unroll
        for (int sub = 0; sub < 2; sub++) {
            const int ch = 2 * s + sub;
            const float* hb = h6[(s % 3) * 2 + sub] + orow * HSTR + xq + 3;
            const float* wp = s_dww + ch * 9;
            float w[9];
#pragma unroll
            for (int i = 0; i < 9; i++) w[i] = wp[i];
            float a[3][6];
#pragma unroll
            for (int dy = 0; dy < 3; dy++)
#pragma unroll
                for (int c = 0; c < 6; c++) a[dy][c] = hb[dy * HSTR + c];
            float4 o;
            o.x = a[0][0]*w[0] + a[0][1]*w[1] + a[0][2]*w[2]
                + a[1][0]*w[3] + a[1][1]*w[4] + a[1][2]*w[5]
                + a[2][0]*w[6] + a[2][1]*w[7] + a[2][2]*w[8];
            o.y = a[0][1]*w[0] + a[0][2]*w[1] + a[0][3]*w[2]
                + a[1][1]*w[3] + a[1][2]*w[4] + a[1][3]*w[5]
                + a[2][1]*w[6] + a[2][2]*w[7] + a[2][3]*w[8];
            o.z = a[0][2]*w[0] + a[0][3]*w[1] + a[0][4]*w[2]
                + a[1][2]*w[3] + a[1][3]*w[4] + a[1][4]*w[5]
                + a[2][2]*w[6] + a[2][3]*w[7] + a[2][4]*w[8];
            o.w = a[0][3]*w[0] + a[0][4]*w[1] + a[0][5]*w[2]
                + a[1][3]*w[3] + a[1][4]*w[4] + a[1][5]*w[5]
                + a[2][3]*w[6] + a[2][4]*w[7] + a[2][5]*w[8];
            *reinterpret_cast<float4*>(wbase + (size_t)ch * 64) = o;
        }
        __syncthreads();
    }
}

// ---------------- window channel-attention (low-smem, 4 CTAs/SM) -------------
#define SQ 68
#define S_ATTN_STRIDE 50
#define AT_OFF   3264
#define QKB_OFF  22656
#define QKB_SZ   6144
#define A_SMEM_BYTES (QKB_OFF + 4 * QKB_SZ)    // 47232

__global__ __launch_bounds__(256) void attn_kernel(
    const float* __restrict__ gwin,          // [(b*8+head)*1024+win][144][64]
    const float* __restrict__ temperature,
    __nv_bfloat16* __restrict__ out_hi,      // [b][hw][384]
    __nv_bfloat16* __restrict__ out_lo)
{
    extern __shared__ float sm[];
    float* s_v    = sm;                      // 48 x SQ (v rows)
    float* s_attn = sm + AT_OFF;             // 48 x 50
    __shared__ __align__(8) uint64_t a_mbar;
    const uint32_t smb = smem_u32(sm);
    const uint32_t qh_b = smb + QKB_OFF;
    const uint32_t kh_b = smb + QKB_OFF + 2 * QKB_SZ;
    char* smc = reinterpret_cast<char*>(sm);

    const int tid  = threadIdx.x;
    const int win  = blockIdx.x;
    const int head = blockIdx.y;
    const int b    = blockIdx.z;
    const int wy = win >> 5, wx = win & 31;
    const int wid = tid >> 5, lane = tid & 31;

    if (tid == 0) MBARRIER_INIT(smem_u32(&a_mbar), 1);
    __syncthreads();

    const float* base = gwin + (((size_t)(b * HEADS + head) * 1024 + win) * 144) * 64;

    if (tid < 32) {
        const uint32_t mb = smem_u32(&a_mbar);
        if (tid == 0) MBARRIER_EXPECT_TX(mb, 48 * 256);
        for (int r = tid; r < 48; r += 32)
            BULK_CPY(smb + (uint32_t)(r * SQ) * 4, base + (size_t)(96 + r) * 64, 256, mb);
    }

    const float temp = __ldg(&temperature[head]);

    // ---- L2 normalize q,k straight from GLOBAL; emit bf16 hi/lo swizzled ----
    {
        const int grp = tid >> 3;
        const int gl  = tid & 7;
#pragma unroll
        for (int it = 0; it < 3; it++) {
            const int r = grp + it * 32;
            const float* gp = base + (size_t)r * 64 + gl * 8;
            float4 v0 = *reinterpret_cast<const float4*>(gp);
            float4 v1 = *reinterpret_cast<const float4*>(gp + 4);
            float s = v0.x * v0.x + v0.y * v0.y + v0.z * v0.z + v0.w * v0.w
                    + v1.x * v1.x + v1.y * v1.y + v1.z * v1.z + v1.w * v1.w;
            s += __shfl_xor_sync(0xffffffffu, s, 1);
            s += __shfl_xor_sync(0xffffffffu, s, 2);
            s += __shfl_xor_sync(0xffffffffu, s, 4);
            const float inv = 1.f / fmaxf(sqrtf(s), 1e-12f);
            float f[8] = { v0.x * inv, v0.y * inv, v0.z * inv, v0.w * inv,
                           v1.x * inv, v1.y * inv, v1.z * inv, v1.w * inv };
            uint32_t hi[4], lo[4];
#pragma unroll
            for (int p = 0; p < 4; p++) {
                __nv_bfloat162 h2 = __floats2bfloat162_rn(f[2 * p], f[2 * p + 1]);
                hi[p] = *reinterpret_cast<uint32_t*>(&h2);
                __nv_bfloat162 l2 = __floats2bfloat162_rn(
                    f[2 * p]     - __bfloat162float(h2.x),
                    f[2 * p + 1] - __bfloat162float(h2.y));
                lo[p] = *reinterpret_cast<uint32_t*>(&l2);
            }
            const int rr = (r < 48) ? r : r - 48;
            const uint32_t bh = ((r < 48) ? (QKB_OFF) : (QKB_OFF + 2 * QKB_SZ)) + swz128r(rr, gl);
            *reinterpret_cast<uint4*>(smc + bh) = make_uint4(hi[0], hi[1], hi[2], hi[3]);
            *reinterpret_cast<uint4*>(smc + bh + QKB_SZ) = make_uint4(lo[0], lo[1], lo[2], lo[3]);
        }
    }
    __syncthreads();

    // ---- QK via HMMA: attn[48][48] = Q . K^T (3-term hi/lo), 6 warps ----
    if (wid < 6) {
        const int wm = (wid >> 1) * 16;
        const int wn = (wid & 1) * 24;
        float acc[3][4];
#pragma unroll
        for (int j = 0; j < 3; j++)
#pragma unroll
            for (int k = 0; k < 4; k++) acc[j][k] = 0.f;

        const int a_r  = wm + (lane & 7) + ((lane >> 3) & 1) * 8;
        const int a_cb = lane >> 4;
        const int b_r  = wn + (lane & 7) + ((lane >> 4) & 1) * 8;
        const int b_cb = (lane >> 3) & 1;
        const int b2_r = wn + 16 + (lane & 7);

#pragma unroll
        for (int k16 = 0; k16 < 4; k16++) {
            uint32_t ah[4], al[4], b4h[4], b4l[4], b2h[2], b2l[2];
            const uint32_t qa = qh_b + swz128r(a_r, k16 * 2 + a_cb);
            ldmx4(ah, qa); ldmx4(al, qa + QKB_SZ);
            const uint32_t ka = kh_b + swz128r(b_r, k16 * 2 + b_cb);
            ldmx4(b4h, ka); ldmx4(b4l, ka + QKB_SZ);
            const uint32_t k2 = kh_b + swz128r(b2_r, k16 * 2 + b_cb);
            ldmx2(b2h, k2); ldmx2(b2l, k2 + QKB_SZ);

            mma16816(acc[0], ah, b4h[0], b4h[1]);
            mma16816(acc[1], ah, b4h[2], b4h[3]);
            mma16816(acc[2], ah, b2h[0], b2h[1]);
            mma16816(acc[0], ah, b4l[0], b4l[1]);
            mma16816(acc[1], ah, b4l[2], b4l[3]);
            mma16816(acc[2], ah, b2l[0], b2l[1]);
            mma16816(acc[0], al, b4h[0], b4h[1]);
            mma16816(acc[1], al, b4h[2], b4h[3]);
            mma16816(acc[2], al, b2h[0], b2h[1]);
        }
        const int row = wm + (lane >> 2);
        const int colb = wn + (lane & 3) * 2;
#pragma unroll
        for (int j = 0; j < 3; j++) {
            const int col = colb + j * 8;
            *reinterpret_cast<float2*>(&s_attn[row * S_ATTN_STRIDE + col]) =
                make_float2(acc[j][0] * temp, acc[j][1] * temp);
            *reinterpret_cast<float2*>(&s_attn[(row + 8) * S_ATTN_STRIDE + col]) =
                make_float2(acc[j][2] * temp, acc[j][3] * temp);
        }
    }
    __syncthreads();

    // ---- softmax over d ----
    {
        for (int r = wid; r < 48; r += 8) {
            const float v0 = s_attn[r * S_ATTN_STRIDE + lane];
            const float v1 = (lane < 16) ? s_attn[r * S_ATTN_STRIDE + lane + 32] : -1e30f;
            float m = fmaxf(v0, v1);
#pragma unroll
            for (int off = 16; off; off >>= 1) m = fmaxf(m, __shfl_xor_sync(0xffffffffu, m, off));
            const float e0 = __expf(v0 - m);
            const float e1 = (lane < 16) ? __expf(v1 - m) : 0.f;
            float s = e0 + e1;
#pragma unroll
            for (int off = 16; off; off >>= 1) s += __shfl_xor_sync(0xffffffffu, s, off);
            const float inv = 1.f / s;
            s_attn[r * S_ATTN_STRIDE + lane] = e0 * inv;
            if (lane < 16) s_attn[r * S_ATTN_STRIDE + lane + 32] = e1 * inv;
        }
    }
    __syncthreads();

    MBARRIER_WAIT_PARITY(smem_u32(&a_mbar), 0);

    // ---- out[c][n] = sum_d attn[c][d] * v[d][n]; out overwrites qk bf16 ----
    float* s_out = reinterpret_cast<float*>(smc + QKB_OFF);
    {
        const int ty = tid >> 4, tx = tid & 15;
        float4 a0c = make_float4(0.f, 0.f, 0.f, 0.f);
        float4 a1c = a0c, a2c = a0c;
        const float* ar0 = s_attn + (ty * 3 + 0) * S_ATTN_STRIDE;
        const float* ar1 = s_attn + (ty * 3 + 1) * S_ATTN_STRIDE;
        const float* ar2 = s_attn + (ty * 3 + 2) * S_ATTN_STRIDE;
#pragma unroll 4
        for (int d = 0; d < 48; ++d) {
            const float a0 = ar0[d], a1 = ar1[d], a2 = ar2[d];
            const float4 v = *reinterpret_cast<const float4*>(&s_v[d * SQ + tx * 4]);
            a0c.x += a0 * v.x; a0c.y += a0 * v.y; a0c.z += a0 * v.z; a0c.w += a0 * v.w;
            a1c.x += a1 * v.x; a1c.y += a1 * v.y; a1c.z += a1 * v.z; a1c.w += a1 * v.w;
            a2c.x += a2 * v.x; a2c.y += a2 * v.y; a2c.z += a2 * v.z; a2c.w += a2 * v.w;
        }
        *reinterpret_cast<float4*>(&s_out[(ty * 3 + 0) * SQ + tx * 4]) = a0c;
        *reinterpret_cast<float4*>(&s_out[(ty * 3 + 1) * SQ + tx * 4]) = a1c;
        *reinterpret_cast<float4*>(&s_out[(ty * 3 + 2) * SQ + tx * 4]) = a2c;
    }
    __syncthreads();

    // ---- write bf16 hi/lo to [b][hw][384] ----
    for (int e = tid; e < 1536; e += 256) {
        const int c2 = e % 24;
        const int n  = e / 24;
        const int c  = c2 * 2;
        const float va = s_out[c * SQ + n];
        const float vb = s_out[(c + 1) * SQ + n];
        const int yy = n >> 3, xx = n & 7;
        const int hw = ((wy * 8 + yy) << 8) + wx * 8 + xx;
        const size_t off = ((size_t)b * HW + hw) * DIMC + head * CPH + c;
        const __nv_bfloat16 ha = __float2bfloat16(va);
        const __nv_bfloat16 hb = __float2bfloat16(vb);
        __nv_bfloat162 hi2, lo2;
        hi2.x = ha; hi2.y = hb;
        lo2.x = __float2bfloat16(va - __bfloat162float(ha));
        lo2.y = __float2bfloat16(vb - __bfloat162float(hb));
        *reinterpret_cast<__nv_bfloat162*>(&out_hi[off]) = hi2;
        *reinterpret_cast<__nv_bfloat162*>(&out_lo[off]) = lo2;
    }
}

// ---------------- launch ----------------------------------------------------
extern "C" void kernel_launch(void* const* d_in, const int* in_sizes, int n_in,
                              void* d_out, int out_size)
{
    const float* x      = (const float*)d_in[0];
    const float* qkv_w  = (const float*)d_in[1];
    const float* dw_w   = (const float*)d_in[2];
    const float* temp   = (const float*)d_in[3];
    const float* proj_w = (const float*)d_in[4];
    const float* proj_b = (const float*)d_in[5];
    float* out = (float*)d_out;

    float *qkv_buf, *win_buf;
    __nv_bfloat16 *xt_hi, *xt_lo, *at_hi, *at_lo, *wq_hi, *wq_lo, *wp_hi, *wp_lo;
    cudaGetSymbolAddress((void**)&qkv_buf, g_qkv);
    cudaGetSymbolAddress((void**)&win_buf, g_win);
    cudaGetSymbolAddress((void**)&xt_hi, g_xt_hi);
    cudaGetSymbolAddress((void**)&xt_lo, g_xt_lo);
    cudaGetSymbolAddress((void**)&at_hi, g_at_hi);
    cudaGetSymbolAddress((void**)&at_lo, g_at_lo);
    cudaGetSymbolAddress((void**)&wq_hi, g_wq_hi);
    cudaGetSymbolAddress((void**)&wq_lo, g_wq_lo);
    cudaGetSymbolAddress((void**)&wp_hi, g_wp_hi);
    cudaGetSymbolAddress((void**)&wp_lo, g_wp_lo);

    cudaFuncSetAttribute(attn_kernel, cudaFuncAttributeMaxDynamicSharedMemorySize, A_SMEM_BYTES);
    cudaFuncSetAttribute(hmma_gemm<0>, cudaFuncAttributeMaxDynamicSharedMemorySize, HG_SMEM);
    cudaFuncSetAttribute(hmma_gemm<1>, cudaFuncAttributeMaxDynamicSharedMemorySize, HG_SMEM);

    // weight splits
    split_w<<<(QKV_M * DIMC + 255) / 256, 256>>>(qkv_w, wq_hi, wq_lo, QKV_M * DIMC);
    split_w<<<(DIMC * DIMC + 255) / 256, 256>>>(proj_w, wp_hi, wp_lo, DIMC * DIMC);

    // x -> transposed hi/lo bf16 [b][hw][384]
    transpose_split<<<dim3(HW / 32, DIMC / 32, BATCH), 256>>>(x, xt_hi, xt_lo, DIMC, HW);

    // qkv = W_qkv . x   -> g_qkv [b][1152][hw] f32
    hmma_gemm<0><<<dim3(QKV_M / 128, HW / 256, BATCH), 256, HG_SMEM>>>(
        wq_hi, wq_lo, xt_hi, xt_lo, qkv_buf, QKV_M, HW, DIMC, nullptr);

    // depthwise 3x3 -> window-major layout
    dwconv_kernel<<<dim3(64, HEADS, BATCH), 256>>>(qkv_buf, dw_w, win_buf);

    // window channel attention -> bf16 hi/lo [b][hw][384]
    attn_kernel<<<dim3(1024, HEADS, BATCH), 256, A_SMEM_BYTES>>>(
        win_buf, temp, at_hi, at_lo);

    // out = W_proj . att + b
    hmma_gemm<1><<<dim3(DIMC / 128, HW / 256, BATCH), 256, HG_SMEM>>>(
        wp_hi, wp_lo, at_hi, at_lo, out, DIMC, HW, DIMC, proj_b);
}

// round 14
// speedup vs baseline: 1.0741x; 1.0741x over previous
#include <cuda_runtime.h>
#include <cuda_bf16.h>
#include <cstdint>
#include <math.h>

// Problem constants
#define DIMC   384
#define HEADS  8
#define CPH    48
#define HH     256
#define WW     256
#define HW     65536
#define BATCH  2
#define QKV_M  1152        // 3*dim

// ---------------- scratch (device globals) ----------------------------------
__device__ float g_qkv[(size_t)BATCH * QKV_M * HW];           // [b][1152][hw] f32
__device__ float g_win[(size_t)BATCH * HEADS * 1024 * 144 * 64]; // window-major dwconv out
__device__ __nv_bfloat16 g_xt_hi[(size_t)BATCH * HW * DIMC];  // [b][hw][384]
__device__ __nv_bfloat16 g_xt_lo[(size_t)BATCH * HW * DIMC];
__device__ __nv_bfloat16 g_at_hi[(size_t)BATCH * HW * DIMC];
__device__ __nv_bfloat16 g_at_lo[(size_t)BATCH * HW * DIMC];
__device__ __nv_bfloat16 g_wq_hi[QKV_M * DIMC], g_wq_lo[QKV_M * DIMC];
__device__ __nv_bfloat16 g_wp_hi[DIMC * DIMC],  g_wp_lo[DIMC * DIMC];

// ---------------- helpers ----------------------------------------------------
__device__ __forceinline__ uint32_t smem_u32(const void* p) {
    uint32_t a;
    asm("{ .reg .u64 t; cvta.to.shared.u64 t, %1; cvt.u32.u64 %0, t; }" : "=r"(a) : "l"(p));
    return a;
}
#define CP_ASYNC16(saddr, gptr) \
    asm volatile("cp.async.cg.shared.global [%0], [%1], 16;" :: "r"(saddr), "l"(gptr))
#define CP_COMMIT() asm volatile("cp.async.commit_group;" ::: "memory")
#define CP_WAIT0()  asm volatile("cp.async.wait_group 0;" ::: "memory")
#define CP_WAIT1()  asm volatile("cp.async.wait_group 1;" ::: "memory")

#define MBARRIER_INIT(addr, cnt) \
    asm volatile("mbarrier.init.shared.b64 [%0], %1;" :: "r"((uint32_t)(addr)), "r"((uint32_t)(cnt)) : "memory")
#define MBARRIER_EXPECT_TX(addr, bytes) \
    asm volatile("mbarrier.arrive.expect_tx.shared.b64 _, [%0], %1;" :: "r"((uint32_t)(addr)), "r"((uint32_t)(bytes)) : "memory")
#define MBARRIER_WAIT_PARITY(mbar_addr, parity) do { \
    uint32_t _mbar = (uint32_t)(mbar_addr); \
    uint32_t _par = (uint32_t)(parity); \
    uint32_t _done; \
    asm volatile( \
        "{\n\t.reg .pred p;\n\t" \
        "mbarrier.try_wait.parity.shared.b64 p, [%1], %2;\n\t" \
        "selp.b32 %0, 1, 0, p;\n\t}" \
        : "=r"(_done) : "r"(_mbar), "r"(_par) : "memory"); \
    if (!_done) { \
        asm volatile( \
            "{\n\t.reg .pred P1;\n\t" \
            "WL_%=:\n\t" \
            "mbarrier.try_wait.parity.shared.b64 P1, [%0], %1;\n\t" \
            "@P1 bra.uni WD_%=;\n\t" \
            "bra.uni WL_%=;\n\t" \
            "WD_%=:\n\t}" \
            :: "r"(_mbar), "r"(_par) : "memory"); \
    } \
} while (0)
#define BULK_CPY(dst_smem, gsrc, bytes, mbar) \
    asm volatile("cp.async.bulk.shared::cta.global.mbarrier::complete_tx::bytes [%0], [%1], %2, [%3];" \
                 :: "r"((uint32_t)(dst_smem)), "l"(gsrc), "r"((uint32_t)(bytes)), "r"((uint32_t)(mbar)) : "memory")
#define FENCE_PROXY_ASYNC() asm volatile("fence.proxy.async.shared::cta;" ::: "memory")

__device__ __forceinline__ void ldmx4(uint32_t* d, uint32_t addr) {
    asm volatile("ldmatrix.sync.aligned.m8n8.x4.shared.b16 {%0,%1,%2,%3}, [%4];"
                 : "=r"(d[0]), "=r"(d[1]), "=r"(d[2]), "=r"(d[3]) : "r"(addr));
}
__device__ __forceinline__ void ldmx2(uint32_t* d, uint32_t addr) {
    asm volatile("ldmatrix.sync.aligned.m8n8.x2.shared.b16 {%0,%1}, [%2];"
                 : "=r"(d[0]), "=r"(d[1]) : "r"(addr));
}
__device__ __forceinline__ void mma16816(float* c, const uint32_t* a, uint32_t b0, uint32_t b1) {
    asm volatile("mma.sync.aligned.m16n8k16.row.col.f32.bf16.bf16.f32 "
                 "{%0,%1,%2,%3}, {%4,%5,%6,%7}, {%8,%9}, {%0,%1,%2,%3};"
                 : "+f"(c[0]), "+f"(c[1]), "+f"(c[2]), "+f"(c[3])
                 : "r"(a[0]), "r"(a[1]), "r"(a[2]), "r"(a[3]), "r"(b0), "r"(b1));
}
__device__ __forceinline__ uint32_t swz(int r, int cb) {          // 64B rows (GEMM tiles)
    return (uint32_t)(r * 64 + ((cb ^ ((r >> 1) & 3)) << 4));
}
__device__ __forceinline__ uint32_t swz128r(int r, int cb) {      // 128B rows (attn bf16)
    return (uint32_t)(r * 128 + ((cb ^ (r & 7)) << 4));
}

// ---------------- transpose + hi/lo bf16 split (for x only) ------------------
__global__ __launch_bounds__(256) void transpose_split(
    const float* __restrict__ in, __nv_bfloat16* __restrict__ hi,
    __nv_bfloat16* __restrict__ lo, int C, int N)
{
    __shared__ float t[32][33];
    const int n0 = blockIdx.x * 32, c0 = blockIdx.y * 32;
    const size_t base = (size_t)blockIdx.z * C * N;
    const int tx = threadIdx.x & 31, ty = threadIdx.x >> 5;
#pragma unroll
    for (int i = 0; i < 4; i++) {
        const int c = ty + i * 8;
        t[c][tx] = in[base + (size_t)(c0 + c) * N + n0 + tx];
    }
    __syncthreads();
#pragma unroll
    for (int i = 0; i < 4; i++) {
        const int n = ty + i * 8;
        const float v = t[tx][n];
        const __nv_bfloat16 h = __float2bfloat16(v);
        const size_t o = base + (size_t)(n0 + n) * C + c0 + tx;
        hi[o] = h;
        lo[o] = __float2bfloat16(v - __bfloat162float(h));
    }
}

__global__ void split_w(const float* __restrict__ w, __nv_bfloat16* __restrict__ hi,
                        __nv_bfloat16* __restrict__ lo, int n)
{
    const int i = blockIdx.x * 256 + threadIdx.x;
    if (i < n) {
        const float v = w[i];
        const __nv_bfloat16 h = __float2bfloat16(v);
        hi[i] = h;
        lo[i] = __float2bfloat16(v - __bfloat162float(h));
    }
}

// ---------------- HMMA GEMM: C[M,N] = A[M,K] . B[N,K]^T ---------------------
// CTA tile 128x128, K-stage 32, 3-stage cp.async ring, one barrier per stage.
#define HG_SMEM 98304

template <int WITH_BIAS>
__global__ __launch_bounds__(256) void hmma_gemm(
    const __nv_bfloat16* __restrict__ Ahi, const __nv_bfloat16* __restrict__ Alo,
    const __nv_bfloat16* __restrict__ Bhi, const __nv_bfloat16* __restrict__ Blo,
    float* __restrict__ Cg, int M, int N, int K, const float* __restrict__ bias)
{
    extern __shared__ char smem[];
    const uint32_t sb = smem_u32(smem);
    const int tid = threadIdx.x;
    const int wid = tid >> 5, lane = tid & 31;
    const int bM = blockIdx.x * 128;
    const int bN = blockIdx.y * 128;
    const size_t bb = (size_t)blockIdx.z * (size_t)N * K;
    float* Cp = Cg + (size_t)blockIdx.z * (size_t)M * N;

    const __nv_bfloat16* Ah = Ahi + (size_t)bM * K;
    const __nv_bfloat16* Al = Alo + (size_t)bM * K;
    const __nv_bfloat16* Bh = Bhi + bb + (size_t)bN * K;
    const __nv_bfloat16* Bl = Blo + bb + (size_t)bN * K;

    const int cb = tid & 3;
    const int r0 = tid >> 2;
    const int nst = K / 32;

#pragma unroll
    for (int ps = 0; ps < 2; ps++) {
        const uint32_t st = sb + ps * 32768;
        const int kk = ps * 32 + cb * 8;
#pragma unroll
        for (int i = 0; i < 2; i++) {
            const int r = r0 + i * 64;
            const uint32_t so = swz(r, cb);
            CP_ASYNC16(st + so,         Ah + (size_t)r * K + kk);
            CP_ASYNC16(st + 8192 + so,  Al + (size_t)r * K + kk);
            CP_ASYNC16(st + 16384 + so, Bh + (size_t)r * K + kk);
            CP_ASYNC16(st + 24576 + so, Bl + (size_t)r * K + kk);
        }
        CP_COMMIT();
    }

    float acc[4][4][4];
#pragma unroll
    for (int i = 0; i < 4; i++)
#pragma unroll
        for (int j = 0; j < 4; j++)
#pragma unroll
            for (int k = 0; k < 4; k++) acc[i][j][k] = 0.f;

    const int wm = (wid >> 2) * 64;
    const int wn = (wid & 3) * 32;
    const int a_rbase = wm + ((lane >> 3) & 1) * 8 + (lane & 7);
    const int a_cbad  = lane >> 4;
    const int b_rbase = wn + ((lane >> 4) & 1) * 8 + (lane & 7);
    const int b_cbad  = (lane >> 3) & 1;

    int sidx = 0;
    for (int s = 0; s < nst; s++) {
        if (s + 1 < nst) CP_WAIT1(); else CP_WAIT0();
        __syncthreads();

        if (s + 2 < nst) {
            int fi = sidx + 2; if (fi >= 3) fi -= 3;
            const uint32_t st = sb + fi * 32768;
            const int kk = (s + 2) * 32 + cb * 8;
#pragma unroll
            for (int i = 0; i < 2; i++) {
                const int r = r0 + i * 64;
                const uint32_t so = swz(r, cb);
                CP_ASYNC16(st + so,         Ah + (size_t)r * K + kk);
                CP_ASYNC16(st + 8192 + so,  Al + (size_t)r * K + kk);
                CP_ASYNC16(st + 16384 + so, Bh + (size_t)r * K + kk);
                CP_ASYNC16(st + 24576 + so, Bl + (size_t)r * K + kk);
            }
            CP_COMMIT();
        }

        const uint32_t st = sb + sidx * 32768;
#pragma unroll
        for (int k16 = 0; k16 < 2; k16++) {
            uint32_t bhf[2][4], blf[2][4];
#pragma unroll
            for (int nh = 0; nh < 2; nh++) {
                const uint32_t ad = st + 16384 + swz(b_rbase + nh * 16, k16 * 2 + b_cbad);
                ldmx4(bhf[nh], ad);
                ldmx4(blf[nh], ad + 8192);
            }
#pragma unroll
            for (int mh = 0; mh < 4; mh++) {
                uint32_t ahf[4], alf[4];
                const uint32_t ad = st + swz(a_rbase + mh * 16, k16 * 2 + a_cbad);
                ldmx4(ahf, ad);
                ldmx4(alf, ad + 8192);
#pragma unroll
                for (int nb = 0; nb < 4; nb++) {
                    const uint32_t* fh = &bhf[nb >> 1][(nb & 1) * 2];
                    const uint32_t* fl = &blf[nb >> 1][(nb & 1) * 2];
                    mma16816(acc[mh][nb], ahf, fh[0], fh[1]);
                    mma16816(acc[mh][nb], ahf, fl[0], fl[1]);
                    mma16816(acc[mh][nb], alf, fh[0], fh[1]);
                }
            }
        }
        if (++sidx == 3) sidx = 0;
    }
    __syncthreads();

    const int row0 = bM + wm + (lane >> 2);
    const int col0 = bN + wn + (lane & 3) * 2;
#pragma unroll
    for (int mh = 0; mh < 4; mh++) {
#pragma unroll
        for (int p = 0; p < 2; p++) {
            const int row = row0 + mh * 16 + p * 8;
            const float bi = WITH_BIAS ? __ldg(&bias[row]) : 0.f;
#pragma unroll
            for (int nb = 0; nb < 4; nb++) {
                float2 v;
                v.x = acc[mh][nb][p * 2 + 0] + bi;
                v.y = acc[mh][nb][p * 2 + 1] + bi;
                *reinterpret_cast<float2*>(&Cp[(size_t)row * N + col0 + nb * 8]) = v;
            }
        }
    }
}

// ---------------- dwconv 3x3 -> window-major (coalesced window stores) -------
#define HSTR 40

__global__ __launch_bounds__(256) void dwconv_kernel(
    const float* __restrict__ qkv1,     // [b][1152][hw]
    const float* __restrict__ dww,      // [1152][9]
    float* __restrict__ gwin)
{
    __shared__ __align__(16) float h6[6][34 * HSTR];
    __shared__ float s_dww[144 * 9];
    __shared__ __align__(8) uint64_t mbar[3];

    const int tid  = threadIdx.x;
    const int tile = blockIdx.x;           // 0..63
    const int head = blockIdx.y;
    const int b    = blockIdx.z;
    const int tyb = tile >> 3, txb = tile & 7;
    const int y0 = tyb * 32 - 1, x0 = txb * 32 - 1;

    const int cs = x0 - 3;
    const int src_off = cs < 0 ? 0 : cs;
    const int dst_off = src_off - cs;
    const int cend = (cs + 40 > 256) ? 256 : (cs + 40);
    const uint32_t rowbytes = (uint32_t)(cend - src_off) * 4;
    const int r_lo = (y0 < 0) ? 1 : 0;
    const int r_hi = (y0 + 33 > 255) ? 32 : 33;
    const uint32_t expect2 = 2u * (uint32_t)(r_hi - r_lo + 1) * rowbytes;

    for (int e = tid; e < 144 * 9; e += 256) {
        const int l = e / 9, kk = e - l * 9;
        const int z = l / 48, cl = l - z * 48;
        s_dww[e] = dww[(size_t)(z * DIMC + head * CPH + cl) * 9 + kk];
    }
    for (int e = tid; e < 6 * 34 * HSTR; e += 256) (&h6[0][0])[e] = 0.f;
    if (tid < 3) MBARRIER_INIT(smem_u32(&mbar[tid]), 1);
    __syncthreads();
    FENCE_PROXY_ASYNC();

    const size_t bbase = (size_t)b * QKV_M * HW;
    const int wid = tid >> 5, lane = tid & 31;

    auto issue = [&](int s) {
        const int slot = s % 3;
        const uint32_t mb = smem_u32(&mbar[slot]);
        if (lane == 0) MBARRIER_EXPECT_TX(mb, expect2);
        for (int i = lane; i < 68; i += 32) {
            const int sub = i / 34;
            const int r = i - sub * 34;
            if (r < r_lo || r > r_hi) continue;
            const int ch = 2 * s + sub;
            const int gc = (ch / 48) * DIMC + head * CPH + (ch % 48);
            const float* srcc = qkv1 + bbase + (size_t)gc * HW;
            BULK_CPY(smem_u32(&h6[slot * 2 + sub][0]) + (uint32_t)(r * HSTR + dst_off) * 4,
                     srcc + (size_t)(y0 + r) * 256 + src_off, rowbytes, mb);
        }
    };
    if (wid == 0) { issue(0); issue(1); }

    // coalesced output mapping: 16 threads per window, contiguous 256B runs
    const int wl = tid >> 4;               // local window 0..15
    const int e0 = (tid & 15) * 4;         // element base 0..60
    const int wy_l = wl >> 2, wx_l = wl & 3;
    const int orow = wy_l * 8 + (e0 >> 3);
    const int xq   = wx_l * 8 + (e0 & 7);
    const int win = (tyb * 4 + wy_l) * 32 + txb * 4 + wx_l;
    float* wbase = gwin + (((size_t)(b * HEADS + head) * 1024 + win) * 144) * 64 + e0;

#pragma unroll 1
    for (int s = 0; s < 72; s++) {
        if (wid == 0 && s + 2 < 72) issue(s + 2);
        MBARRIER_WAIT_PARITY(smem_u32(&mbar[s % 3]), (s / 3) & 1);

#pragma unroll
        for (int sub = 0; sub < 2; sub++) {
            const int ch = 2 * s + sub;
            const float* hb = h6[(s % 3) * 2 + sub] + orow * HSTR + xq + 3;
            const float* wp = s_dww + ch * 9;
            float w[9];
#pragma unroll
            for (int i = 0; i < 9; i++) w[i] = wp[i];
            float a[3][6];
#pragma unroll
            for (int dy = 0; dy < 3; dy++)
#pragma unroll
                for (int c = 0; c < 6; c++) a[dy][c] = hb[dy * HSTR + c];
            float4 o;
            o.x = a[0][0]*w[0] + a[0][1]*w[1] + a[0][2]*w[2]
                + a[1][0]*w[3] + a[1][1]*w[4] + a[1][2]*w[5]
                + a[2][0]*w[6] + a[2][1]*w[7] + a[2][2]*w[8];
            o.y = a[0][1]*w[0] + a[0][2]*w[1] + a[0][3]*w[2]
                + a[1][1]*w[3] + a[1][2]*w[4] + a[1][3]*w[5]
                + a[2][1]*w[6] + a[2][2]*w[7] + a[2][3]*w[8];
            o.z = a[0][2]*w[0] + a[0][3]*w[1] + a[0][4]*w[2]
                + a[1][2]*w[3] + a[1][3]*w[4] + a[1][4]*w[5]
                + a[2][2]*w[6] + a[2][3]*w[7] + a[2][4]*w[8];
            o.w = a[0][3]*w[0] + a[0][4]*w[1] + a[0][5]*w[2]
                + a[1][3]*w[3] + a[1][4]*w[4] + a[1][5]*w[5]
                + a[2][3]*w[6] + a[2][4]*w[7] + a[2][5]*w[8];
            *reinterpret_cast<float4*>(wbase + (size_t)ch * 64) = o;
        }
        __syncthreads();
    }
}

// ---------------- window channel-attention (low-smem, 4 CTAs/SM) -------------
#define SQ 68
#define S_ATTN_STRIDE 50
#define AT_OFF   3264
#define QKB_OFF  22656
#define QKB_SZ   6144
#define A_SMEM_BYTES (QKB_OFF + 4 * QKB_SZ)    // 47232

__global__ __launch_bounds__(256) void attn_kernel(
    const float* __restrict__ gwin,          // [(b*8+head)*1024+win][144][64]
    const float* __restrict__ temperature,
    __nv_bfloat16* __restrict__ out_hi,      // [b][hw][384]
    __nv_bfloat16* __restrict__ out_lo)
{
    extern __shared__ float sm[];
    float* s_v    = sm;                      // 48 x SQ (v rows)
    float* s_attn = sm + AT_OFF;             // 48 x 50
    __shared__ __align__(8) uint64_t a_mbar;
    const uint32_t smb = smem_u32(sm);
    const uint32_t qh_b = smb + QKB_OFF;
    const uint32_t kh_b = smb + QKB_OFF + 2 * QKB_SZ;
    char* smc = reinterpret_cast<char*>(sm);

    const int tid  = threadIdx.x;
    const int win  = blockIdx.x;
    const int head = blockIdx.y;
    const int b    = blockIdx.z;
    const int wy = win >> 5, wx = win & 31;
    const int wid = tid >> 5, lane = tid & 31;

    if (tid == 0) MBARRIER_INIT(smem_u32(&a_mbar), 1);
    __syncthreads();

    const float* base = gwin + (((size_t)(b * HEADS + head) * 1024 + win) * 144) * 64;

    if (tid < 32) {
        const uint32_t mb = smem_u32(&a_mbar);
        if (tid == 0) MBARRIER_EXPECT_TX(mb, 48 * 256);
        for (int r = tid; r < 48; r += 32)
            BULK_CPY(smb + (uint32_t)(r * SQ) * 4, base + (size_t)(96 + r) * 64, 256, mb);
    }

    const float temp = __ldg(&temperature[head]);

    // ---- L2 normalize q,k straight from GLOBAL; emit bf16 hi/lo swizzled ----
    {
        const int grp = tid >> 3;
        const int gl  = tid & 7;
#pragma unroll
        for (int it = 0; it < 3; it++) {
            const int r = grp + it * 32;
            const float* gp = base + (size_t)r * 64 + gl * 8;
            float4 v0 = *reinterpret_cast<const float4*>(gp);
            float4 v1 = *reinterpret_cast<const float4*>(gp + 4);
            float s = v0.x * v0.x + v0.y * v0.y + v0.z * v0.z + v0.w * v0.w
                    + v1.x * v1.x + v1.y * v1.y + v1.z * v1.z + v1.w * v1.w;
            s += __shfl_xor_sync(0xffffffffu, s, 1);
            s += __shfl_xor_sync(0xffffffffu, s, 2);
            s += __shfl_xor_sync(0xffffffffu, s, 4);
            const float inv = 1.f / fmaxf(sqrtf(s), 1e-12f);
            float f[8] = { v0.x * inv, v0.y * inv, v0.z * inv, v0.w * inv,
                           v1.x * inv, v1.y * inv, v1.z * inv, v1.w * inv };
            uint32_t hi[4], lo[4];
#pragma unroll
            for (int p = 0; p < 4; p++) {
                __nv_bfloat162 h2 = __floats2bfloat162_rn(f[2 * p], f[2 * p + 1]);
                hi[p] = *reinterpret_cast<uint32_t*>(&h2);
                __nv_bfloat162 l2 = __floats2bfloat162_rn(
                    f[2 * p]     - __bfloat162float(h2.x),
                    f[2 * p + 1] - __bfloat162float(h2.y));
                lo[p] = *reinterpret_cast<uint32_t*>(&l2);
            }
            const int rr = (r < 48) ? r : r - 48;
            const uint32_t bh = ((r < 48) ? (QKB_OFF) : (QKB_OFF + 2 * QKB_SZ)) + swz128r(rr, gl);
            *reinterpret_cast<uint4*>(smc + bh) = make_uint4(hi[0], hi[1], hi[2], hi[3]);
            *reinterpret_cast<uint4*>(smc + bh + QKB_SZ) = make_uint4(lo[0], lo[1], lo[2], lo[3]);
        }
    }
    __syncthreads();

    // ---- QK via HMMA: attn[48][48] = Q . K^T (3-term hi/lo), 6 warps ----
    if (wid < 6) {
        const int wm = (wid >> 1) * 16;
        const int wn = (wid & 1) * 24;
        float acc[3][4];
#pragma unroll
        for (int j = 0; j < 3; j++)
#pragma unroll
            for (int k = 0; k < 4; k++) acc[j][k] = 0.f;

        const int a_r  = wm + (lane & 7) + ((lane >> 3) & 1) * 8;
        const int a_cb = lane >> 4;
        const int b_r  = wn + (lane & 7) + ((lane >> 4) & 1) * 8;
        const int b_cb = (lane >> 3) & 1;
        const int b2_r = wn + 16 + (lane & 7);

#pragma unroll
        for (int k16 = 0; k16 < 4; k16++) {
            uint32_t ah[4], al[4], b4h[4], b4l[4], b2h[2], b2l[2];
            const uint32_t qa = qh_b + swz128r(a_r, k16 * 2 + a_cb);
            ldmx4(ah, qa); ldmx4(al, qa + QKB_SZ);
            const uint32_t ka = kh_b + swz128r(b_r, k16 * 2 + b_cb);
            ldmx4(b4h, ka); ldmx4(b4l, ka + QKB_SZ);
            const uint32_t k2 = kh_b + swz128r(b2_r, k16 * 2 + b_cb);
            ldmx2(b2h, k2); ldmx2(b2l, k2 + QKB_SZ);

            mma16816(acc[0], ah, b4h[0], b4h[1]);
            mma16816(acc[1], ah, b4h[2], b4h[3]);
            mma16816(acc[2], ah, b2h[0], b2h[1]);
            mma16816(acc[0], ah, b4l[0], b4l[1]);
            mma16816(acc[1], ah, b4l[2], b4l[3]);
            mma16816(acc[2], ah, b2l[0], b2l[1]);
            mma16816(acc[0], al, b4h[0], b4h[1]);
            mma16816(acc[1], al, b4h[2], b4h[3]);
            mma16816(acc[2], al, b2h[0], b2h[1]);
        }
        const int row = wm + (lane >> 2);
        const int colb = wn + (lane & 3) * 2;
#pragma unroll
        for (int j = 0; j < 3; j++) {
            const int col = colb + j * 8;
            *reinterpret_cast<float2*>(&s_attn[row * S_ATTN_STRIDE + col]) =
                make_float2(acc[j][0] * temp, acc[j][1] * temp);
            *reinterpret_cast<float2*>(&s_attn[(row + 8) * S_ATTN_STRIDE + col]) =
                make_float2(acc[j][2] * temp, acc[j][3] * temp);
        }
    }
    __syncthreads();

    // ---- softmax over d ----
    {
        for (int r = wid; r < 48; r += 8) {
            const float v0 = s_attn[r * S_ATTN_STRIDE + lane];
            const float v1 = (lane < 16) ? s_attn[r * S_ATTN_STRIDE + lane + 32] : -1e30f;
            float m = fmaxf(v0, v1);
#pragma unroll
            for (int off = 16; off; off >>= 1) m = fmaxf(m, __shfl_xor_sync(0xffffffffu, m, off));
            const float e0 = __expf(v0 - m);
            const float e1 = (lane < 16) ? __expf(v1 - m) : 0.f;
            float s = e0 + e1;
#pragma unroll
            for (int off = 16; off; off >>= 1) s += __shfl_xor_sync(0xffffffffu, s, off);
            const float inv = 1.f / s;
            s_attn[r * S_ATTN_STRIDE + lane] = e0 * inv;
            if (lane < 16) s_attn[r * S_ATTN_STRIDE + lane + 32] = e1 * inv;
        }
    }
    __syncthreads();

    MBARRIER_WAIT_PARITY(smem_u32(&a_mbar), 0);

    // ---- out[c][n] = sum_d attn[c][d] * v[d][n]; out overwrites qk bf16 ----
    float* s_out = reinterpret_cast<float*>(smc + QKB_OFF);
    {
        const int ty = tid >> 4, tx = tid & 15;
        float4 a0c = make_float4(0.f, 0.f, 0.f, 0.f);
        float4 a1c = a0c, a2c = a0c;
        const float* ar0 = s_attn + (ty * 3 + 0) * S_ATTN_STRIDE;
        const float* ar1 = s_attn + (ty * 3 + 1) * S_ATTN_STRIDE;
        const float* ar2 = s_attn + (ty * 3 + 2) * S_ATTN_STRIDE;
#pragma unroll 4
        for (int d = 0; d < 48; ++d) {
            const float a0 = ar0[d], a1 = ar1[d], a2 = ar2[d];
            const float4 v = *reinterpret_cast<const float4*>(&s_v[d * SQ + tx * 4]);
            a0c.x += a0 * v.x; a0c.y += a0 * v.y; a0c.z += a0 * v.z; a0c.w += a0 * v.w;
            a1c.x += a1 * v.x; a1c.y += a1 * v.y; a1c.z += a1 * v.z; a1c.w += a1 * v.w;
            a2c.x += a2 * v.x; a2c.y += a2 * v.y; a2c.z += a2 * v.z; a2c.w += a2 * v.w;
        }
        *reinterpret_cast<float4*>(&s_out[(ty * 3 + 0) * SQ + tx * 4]) = a0c;
        *reinterpret_cast<float4*>(&s_out[(ty * 3 + 1) * SQ + tx * 4]) = a1c;
        *reinterpret_cast<float4*>(&s_out[(ty * 3 + 2) * SQ + tx * 4]) = a2c;
    }
    __syncthreads();

    // ---- write bf16 hi/lo to [b][hw][384] ----
    for (int e = tid; e < 1536; e += 256) {
        const int c2 = e % 24;
        const int n  = e / 24;
        const int c  = c2 * 2;
        const float va = s_out[c * SQ + n];
        const float vb = s_out[(c + 1) * SQ + n];
        const int yy = n >> 3, xx = n & 7;
        const int hw = ((wy * 8 + yy) << 8) + wx * 8 + xx;
        const size_t off = ((size_t)b * HW + hw) * DIMC + head * CPH + c;
        const __nv_bfloat16 ha = __float2bfloat16(va);
        const __nv_bfloat16 hb = __float2bfloat16(vb);
        __nv_bfloat162 hi2, lo2;
        hi2.x = ha; hi2.y = hb;
        lo2.x = __float2bfloat16(va - __bfloat162float(ha));
        lo2.y = __float2bfloat16(vb - __bfloat162float(hb));
        *reinterpret_cast<__nv_bfloat162*>(&out_hi[off]) = hi2;
        *reinterpret_cast<__nv_bfloat162*>(&out_lo[off]) = lo2;
    }
}

// ---------------- launch ----------------------------------------------------
extern "C" void kernel_launch(void* const* d_in, const int* in_sizes, int n_in,
                              void* d_out, int out_size)
{
    const float* x      = (const float*)d_in[0];
    const float* qkv_w  = (const float*)d_in[1];
    const float* dw_w   = (const float*)d_in[2];
    const float* temp   = (const float*)d_in[3];
    const float* proj_w = (const float*)d_in[4];
    const float* proj_b = (const float*)d_in[5];
    float* out = (float*)d_out;

    float *qkv_buf, *win_buf;
    __nv_bfloat16 *xt_hi, *xt_lo, *at_hi, *at_lo, *wq_hi, *wq_lo, *wp_hi, *wp_lo;
    cudaGetSymbolAddress((void**)&qkv_buf, g_qkv);
    cudaGetSymbolAddress((void**)&win_buf, g_win);
    cudaGetSymbolAddress((void**)&xt_hi, g_xt_hi);
    cudaGetSymbolAddress((void**)&xt_lo, g_xt_lo);
    cudaGetSymbolAddress((void**)&at_hi, g_at_hi);
    cudaGetSymbolAddress((void**)&at_lo, g_at_lo);
    cudaGetSymbolAddress((void**)&wq_hi, g_wq_hi);
    cudaGetSymbolAddress((void**)&wq_lo, g_wq_lo);
    cudaGetSymbolAddress((void**)&wp_hi, g_wp_hi);
    cudaGetSymbolAddress((void**)&wp_lo, g_wp_lo);

    cudaFuncSetAttribute(attn_kernel, cudaFuncAttributeMaxDynamicSharedMemorySize, A_SMEM_BYTES);
    cudaFuncSetAttribute(hmma_gemm<0>, cudaFuncAttributeMaxDynamicSharedMemorySize, HG_SMEM);
    cudaFuncSetAttribute(hmma_gemm<1>, cudaFuncAttributeMaxDynamicSharedMemorySize, HG_SMEM);

    // weight splits
    split_w<<<(QKV_M * DIMC + 255) / 256, 256>>>(qkv_w, wq_hi, wq_lo, QKV_M * DIMC);
    split_w<<<(DIMC * DIMC + 255) / 256, 256>>>(proj_w, wp_hi, wp_lo, DIMC * DIMC);

    // x -> transposed hi/lo bf16 [b][hw][384]
    transpose_split<<<dim3(HW / 32, DIMC / 32, BATCH), 256>>>(x, xt_hi, xt_lo, DIMC, HW);

    // qkv = W_qkv . x   -> g_qkv [b][1152][hw] f32
    hmma_gemm<0><<<dim3(QKV_M / 128, HW / 128, BATCH), 256, HG_SMEM>>>(
        wq_hi, wq_lo, xt_hi, xt_lo, qkv_buf, QKV_M, HW, DIMC, nullptr);

    // depthwise 3x3 -> window-major layout
    dwconv_kernel<<<dim3(64, HEADS, BATCH), 256>>>(qkv_buf, dw_w, win_buf);

    // window channel attention -> bf16 hi/lo [b][hw][384]
    attn_kernel<<<dim3(1024, HEADS, BATCH), 256, A_SMEM_BYTES>>>(
        win_buf, temp, at_hi, at_lo);

    // out = W_proj . att + b
    hmma_gemm<1><<<dim3(DIMC / 128, HW / 128, BATCH), 256, HG_SMEM>>>(
        wp_hi, wp_lo, at_hi, at_lo, out, DIMC, HW, DIMC, proj_b);
}

// round 15
// speedup vs baseline: 1.4062x; 1.3093x over previous
#include <cuda_runtime.h>
#include <cuda_bf16.h>
#include <cuda_fp16.h>
#include <cstdint>
#include <math.h>

// Problem constants
#define DIMC   384
#define HEADS  8
#define CPH    48
#define HH     256
#define WW     256
#define HW     65536
#define BATCH  2
#define QKV_M  1152        // 3*dim

// ---------------- scratch (device globals) ----------------------------------
__device__ float g_qkv[(size_t)BATCH * QKV_M * HW];           // [b][1152][hw] f32
__device__ float g_win[(size_t)BATCH * HEADS * 1024 * 144 * 64]; // window-major dwconv out
__device__ __half g_xt_h[(size_t)BATCH * HW * DIMC];          // [b][hw][384] fp16
__device__ __half g_wq_h[QKV_M * DIMC];                       // fp16 weights
__device__ __nv_bfloat16 g_at_hi[(size_t)BATCH * HW * DIMC];  // [b][hw][384]
__device__ __nv_bfloat16 g_at_lo[(size_t)BATCH * HW * DIMC];
__device__ __nv_bfloat16 g_wp_hi[DIMC * DIMC],  g_wp_lo[DIMC * DIMC];

// ---------------- helpers ----------------------------------------------------
__device__ __forceinline__ uint32_t smem_u32(const void* p) {
    uint32_t a;
    asm("{ .reg .u64 t; cvta.to.shared.u64 t, %1; cvt.u32.u64 %0, t; }" : "=r"(a) : "l"(p));
    return a;
}
#define CP_ASYNC16(saddr, gptr) \
    asm volatile("cp.async.cg.shared.global [%0], [%1], 16;" :: "r"(saddr), "l"(gptr))
#define CP_COMMIT() asm volatile("cp.async.commit_group;" ::: "memory")
#define CP_WAIT0()  asm volatile("cp.async.wait_group 0;" ::: "memory")
#define CP_WAIT1()  asm volatile("cp.async.wait_group 1;" ::: "memory")

#define MBARRIER_INIT(addr, cnt) \
    asm volatile("mbarrier.init.shared.b64 [%0], %1;" :: "r"((uint32_t)(addr)), "r"((uint32_t)(cnt)) : "memory")
#define MBARRIER_EXPECT_TX(addr, bytes) \
    asm volatile("mbarrier.arrive.expect_tx.shared.b64 _, [%0], %1;" :: "r"((uint32_t)(addr)), "r"((uint32_t)(bytes)) : "memory")
#define MBARRIER_WAIT_PARITY(mbar_addr, parity) do { \
    uint32_t _mbar = (uint32_t)(mbar_addr); \
    uint32_t _par = (uint32_t)(parity); \
    uint32_t _done; \
    asm volatile( \
        "{\n\t.reg .pred p;\n\t" \
        "mbarrier.try_wait.parity.shared.b64 p, [%1], %2;\n\t" \
        "selp.b32 %0, 1, 0, p;\n\t}" \
        : "=r"(_done) : "r"(_mbar), "r"(_par) : "memory"); \
    if (!_done) { \
        asm volatile( \
            "{\n\t.reg .pred P1;\n\t" \
            "WL_%=:\n\t" \
            "mbarrier.try_wait.parity.shared.b64 P1, [%0], %1;\n\t" \
            "@P1 bra.uni WD_%=;\n\t" \
            "bra.uni WL_%=;\n\t" \
            "WD_%=:\n\t}" \
            :: "r"(_mbar), "r"(_par) : "memory"); \
    } \
} while (0)
#define BULK_CPY(dst_smem, gsrc, bytes, mbar) \
    asm volatile("cp.async.bulk.shared::cta.global.mbarrier::complete_tx::bytes [%0], [%1], %2, [%3];" \
                 :: "r"((uint32_t)(dst_smem)), "l"(gsrc), "r"((uint32_t)(bytes)), "r"((uint32_t)(mbar)) : "memory")
#define FENCE_PROXY_ASYNC() asm volatile("fence.proxy.async.shared::cta;" ::: "memory")

__device__ __forceinline__ void ldmx4(uint32_t* d, uint32_t addr) {
    asm volatile("ldmatrix.sync.aligned.m8n8.x4.shared.b16 {%0,%1,%2,%3}, [%4];"
                 : "=r"(d[0]), "=r"(d[1]), "=r"(d[2]), "=r"(d[3]) : "r"(addr));
}
__device__ __forceinline__ void ldmx2(uint32_t* d, uint32_t addr) {
    asm volatile("ldmatrix.sync.aligned.m8n8.x2.shared.b16 {%0,%1}, [%2];"
                 : "=r"(d[0]), "=r"(d[1]) : "r"(addr));
}
__device__ __forceinline__ void mma16816(float* c, const uint32_t* a, uint32_t b0, uint32_t b1) {
    asm volatile("mma.sync.aligned.m16n8k16.row.col.f32.bf16.bf16.f32 "
                 "{%0,%1,%2,%3}, {%4,%5,%6,%7}, {%8,%9}, {%0,%1,%2,%3};"
                 : "+f"(c[0]), "+f"(c[1]), "+f"(c[2]), "+f"(c[3])
                 : "r"(a[0]), "r"(a[1]), "r"(a[2]), "r"(a[3]), "r"(b0), "r"(b1));
}
__device__ __forceinline__ void mma16816h(float* c, const uint32_t* a, uint32_t b0, uint32_t b1) {
    asm volatile("mma.sync.aligned.m16n8k16.row.col.f32.f16.f16.f32 "
                 "{%0,%1,%2,%3}, {%4,%5,%6,%7}, {%8,%9}, {%0,%1,%2,%3};"
                 : "+f"(c[0]), "+f"(c[1]), "+f"(c[2]), "+f"(c[3])
                 : "r"(a[0]), "r"(a[1]), "r"(a[2]), "r"(a[3]), "r"(b0), "r"(b1));
}
__device__ __forceinline__ uint32_t swz(int r, int cb) {          // 64B rows (GEMM tiles)
    return (uint32_t)(r * 64 + ((cb ^ ((r >> 1) & 3)) << 4));
}
__device__ __forceinline__ uint32_t swz128r(int r, int cb) {      // 128B rows (attn bf16)
    return (uint32_t)(r * 128 + ((cb ^ (r & 7)) << 4));
}

// ---------------- transpose to fp16 (for x / GEMM1 B operand) ----------------
__global__ __launch_bounds__(256) void transpose_h(
    const float* __restrict__ in, __half* __restrict__ outp, int C, int N)
{
    __shared__ float t[32][33];
    const int n0 = blockIdx.x * 32, c0 = blockIdx.y * 32;
    const size_t base = (size_t)blockIdx.z * C * N;
    const int tx = threadIdx.x & 31, ty = threadIdx.x >> 5;
#pragma unroll
    for (int i = 0; i < 4; i++) {
        const int c = ty + i * 8;
        t[c][tx] = in[base + (size_t)(c0 + c) * N + n0 + tx];
    }
    __syncthreads();
#pragma unroll
    for (int i = 0; i < 4; i++) {
        const int n = ty + i * 8;
        outp[base + (size_t)(n0 + n) * C + c0 + tx] = __float2half(t[tx][n]);
    }
}

__global__ void split_w(const float* __restrict__ w, __nv_bfloat16* __restrict__ hi,
                        __nv_bfloat16* __restrict__ lo, int n)
{
    const int i = blockIdx.x * 256 + threadIdx.x;
    if (i < n) {
        const float v = w[i];
        const __nv_bfloat16 h = __float2bfloat16(v);
        hi[i] = h;
        lo[i] = __float2bfloat16(v - __bfloat162float(h));
    }
}

__global__ void conv_w_h(const float* __restrict__ w, __half* __restrict__ outp, int n)
{
    const int i = blockIdx.x * 256 + threadIdx.x;
    if (i < n) outp[i] = __float2half(w[i]);
}

// ---------------- fp16 single-pass GEMM (GEMM1): C = A . B^T ----------------
// A [M][K] fp16, B per-batch [N][K] fp16, C [M][N] f32.
// CTA tile 128x128, K-stage 32, 3-stage ring; stage = A 8K + B 8K = 16K.
#define HG1_SMEM 49152

__global__ __launch_bounds__(256) void hmma_gemm_f16(
    const __half* __restrict__ Ag, const __half* __restrict__ Bg,
    float* __restrict__ Cg, int M, int N, int K)
{
    extern __shared__ char smem[];
    const uint32_t sb = smem_u32(smem);
    const int tid = threadIdx.x;
    const int wid = tid >> 5, lane = tid & 31;
    const int bM = blockIdx.x * 128;
    const int bN = blockIdx.y * 128;
    const size_t bb = (size_t)blockIdx.z * (size_t)N * K;
    float* Cp = Cg + (size_t)blockIdx.z * (size_t)M * N;

    const __half* A = Ag + (size_t)bM * K;
    const __half* B = Bg + bb + (size_t)bN * K;

    const int cb = tid & 3;
    const int r0 = tid >> 2;      // 0..63
    const int nst = K / 32;       // 12

#pragma unroll
    for (int ps = 0; ps < 2; ps++) {
        const uint32_t st = sb + ps * 16384;
        const int kk = ps * 32 + cb * 8;
#pragma unroll
        for (int i = 0; i < 2; i++) {
            const int r = r0 + i * 64;
            const uint32_t so = swz(r, cb);
            CP_ASYNC16(st + so,        A + (size_t)r * K + kk);
            CP_ASYNC16(st + 8192 + so, B + (size_t)r * K + kk);
        }
        CP_COMMIT();
    }

    float acc[4][4][4];
#pragma unroll
    for (int i = 0; i < 4; i++)
#pragma unroll
        for (int j = 0; j < 4; j++)
#pragma unroll
            for (int k = 0; k < 4; k++) acc[i][j][k] = 0.f;

    const int wm = (wid >> 2) * 64;
    const int wn = (wid & 3) * 32;
    const int a_rbase = wm + ((lane >> 3) & 1) * 8 + (lane & 7);
    const int a_cbad  = lane >> 4;
    const int b_rbase = wn + ((lane >> 4) & 1) * 8 + (lane & 7);
    const int b_cbad  = (lane >> 3) & 1;

    int sidx = 0;
    for (int s = 0; s < nst; s++) {
        if (s + 1 < nst) CP_WAIT1(); else CP_WAIT0();
        __syncthreads();

        if (s + 2 < nst) {
            int fi = sidx + 2; if (fi >= 3) fi -= 3;
            const uint32_t st = sb + fi * 16384;
            const int kk = (s + 2) * 32 + cb * 8;
#pragma unroll
            for (int i = 0; i < 2; i++) {
                const int r = r0 + i * 64;
                const uint32_t so = swz(r, cb);
                CP_ASYNC16(st + so,        A + (size_t)r * K + kk);
                CP_ASYNC16(st + 8192 + so, B + (size_t)r * K + kk);
            }
            CP_COMMIT();
        }

        const uint32_t st = sb + sidx * 16384;
#pragma unroll
        for (int k16 = 0; k16 < 2; k16++) {
            uint32_t bf[2][4];
#pragma unroll
            for (int nh = 0; nh < 2; nh++)
                ldmx4(bf[nh], st + 8192 + swz(b_rbase + nh * 16, k16 * 2 + b_cbad));
#pragma unroll
            for (int mh = 0; mh < 4; mh++) {
                uint32_t af[4];
                ldmx4(af, st + swz(a_rbase + mh * 16, k16 * 2 + a_cbad));
#pragma unroll
                for (int nb = 0; nb < 4; nb++) {
                    const uint32_t* f = &bf[nb >> 1][(nb & 1) * 2];
                    mma16816h(acc[mh][nb], af, f[0], f[1]);
                }
            }
        }
        if (++sidx == 3) sidx = 0;
    }
    __syncthreads();

    const int row0 = bM + wm + (lane >> 2);
    const int col0 = bN + wn + (lane & 3) * 2;
#pragma unroll
    for (int mh = 0; mh < 4; mh++) {
#pragma unroll
        for (int p = 0; p < 2; p++) {
            const int row = row0 + mh * 16 + p * 8;
#pragma unroll
            for (int nb = 0; nb < 4; nb++) {
                float2 v;
                v.x = acc[mh][nb][p * 2 + 0];
                v.y = acc[mh][nb][p * 2 + 1];
                *reinterpret_cast<float2*>(&Cp[(size_t)row * N + col0 + nb * 8]) = v;
            }
        }
    }
}

// ---------------- bf16 3-term GEMM (GEMM2): C = A . B^T + bias --------------
#define HG_SMEM 98304

__global__ __launch_bounds__(256) void hmma_gemm(
    const __nv_bfloat16* __restrict__ Ahi, const __nv_bfloat16* __restrict__ Alo,
    const __nv_bfloat16* __restrict__ Bhi, const __nv_bfloat16* __restrict__ Blo,
    float* __restrict__ Cg, int M, int N, int K, const float* __restrict__ bias)
{
    extern __shared__ char smem[];
    const uint32_t sb = smem_u32(smem);
    const int tid = threadIdx.x;
    const int wid = tid >> 5, lane = tid & 31;
    const int bM = blockIdx.x * 128;
    const int bN = blockIdx.y * 128;
    const size_t bb = (size_t)blockIdx.z * (size_t)N * K;
    float* Cp = Cg + (size_t)blockIdx.z * (size_t)M * N;

    const __nv_bfloat16* Ah = Ahi + (size_t)bM * K;
    const __nv_bfloat16* Al = Alo + (size_t)bM * K;
    const __nv_bfloat16* Bh = Bhi + bb + (size_t)bN * K;
    const __nv_bfloat16* Bl = Blo + bb + (size_t)bN * K;

    const int cb = tid & 3;
    const int r0 = tid >> 2;
    const int nst = K / 32;

#pragma unroll
    for (int ps = 0; ps < 2; ps++) {
        const uint32_t st = sb + ps * 32768;
        const int kk = ps * 32 + cb * 8;
#pragma unroll
        for (int i = 0; i < 2; i++) {
            const int r = r0 + i * 64;
            const uint32_t so = swz(r, cb);
            CP_ASYNC16(st + so,         Ah + (size_t)r * K + kk);
            CP_ASYNC16(st + 8192 + so,  Al + (size_t)r * K + kk);
            CP_ASYNC16(st + 16384 + so, Bh + (size_t)r * K + kk);
            CP_ASYNC16(st + 24576 + so, Bl + (size_t)r * K + kk);
        }
        CP_COMMIT();
    }

    float acc[4][4][4];
#pragma unroll
    for (int i = 0; i < 4; i++)
#pragma unroll
        for (int j = 0; j < 4; j++)
#pragma unroll
            for (int k = 0; k < 4; k++) acc[i][j][k] = 0.f;

    const int wm = (wid >> 2) * 64;
    const int wn = (wid & 3) * 32;
    const int a_rbase = wm + ((lane >> 3) & 1) * 8 + (lane & 7);
    const int a_cbad  = lane >> 4;
    const int b_rbase = wn + ((lane >> 4) & 1) * 8 + (lane & 7);
    const int b_cbad  = (lane >> 3) & 1;

    int sidx = 0;
    for (int s = 0; s < nst; s++) {
        if (s + 1 < nst) CP_WAIT1(); else CP_WAIT0();
        __syncthreads();

        if (s + 2 < nst) {
            int fi = sidx + 2; if (fi >= 3) fi -= 3;
            const uint32_t st = sb + fi * 32768;
            const int kk = (s + 2) * 32 + cb * 8;
#pragma unroll
            for (int i = 0; i < 2; i++) {
                const int r = r0 + i * 64;
                const uint32_t so = swz(r, cb);
                CP_ASYNC16(st + so,         Ah + (size_t)r * K + kk);
                CP_ASYNC16(st + 8192 + so,  Al + (size_t)r * K + kk);
                CP_ASYNC16(st + 16384 + so, Bh + (size_t)r * K + kk);
                CP_ASYNC16(st + 24576 + so, Bl + (size_t)r * K + kk);
            }
            CP_COMMIT();
        }

        const uint32_t st = sb + sidx * 32768;
#pragma unroll
        for (int k16 = 0; k16 < 2; k16++) {
            uint32_t bhf[2][4], blf[2][4];
#pragma unroll
            for (int nh = 0; nh < 2; nh++) {
                const uint32_t ad = st + 16384 + swz(b_rbase + nh * 16, k16 * 2 + b_cbad);
                ldmx4(bhf[nh], ad);
                ldmx4(blf[nh], ad + 8192);
            }
#pragma unroll
            for (int mh = 0; mh < 4; mh++) {
                uint32_t ahf[4], alf[4];
                const uint32_t ad = st + swz(a_rbase + mh * 16, k16 * 2 + a_cbad);
                ldmx4(ahf, ad);
                ldmx4(alf, ad + 8192);
#pragma unroll
                for (int nb = 0; nb < 4; nb++) {
                    const uint32_t* fh = &bhf[nb >> 1][(nb & 1) * 2];
                    const uint32_t* fl = &blf[nb >> 1][(nb & 1) * 2];
                    mma16816(acc[mh][nb], ahf, fh[0], fh[1]);
                    mma16816(acc[mh][nb], ahf, fl[0], fl[1]);
                    mma16816(acc[mh][nb], alf, fh[0], fh[1]);
                }
            }
        }
        if (++sidx == 3) sidx = 0;
    }
    __syncthreads();

    const int row0 = bM + wm + (lane >> 2);
    const int col0 = bN + wn + (lane & 3) * 2;
#pragma unroll
    for (int mh = 0; mh < 4; mh++) {
#pragma unroll
        for (int p = 0; p < 2; p++) {
            const int row = row0 + mh * 16 + p * 8;
            const float bi = __ldg(&bias[row]);
#pragma unroll
            for (int nb = 0; nb < 4; nb++) {
                float2 v;
                v.x = acc[mh][nb][p * 2 + 0] + bi;
                v.y = acc[mh][nb][p * 2 + 1] + bi;
                *reinterpret_cast<float2*>(&Cp[(size_t)row * N + col0 + nb * 8]) = v;
            }
        }
    }
}

// ---------------- dwconv 3x3 -> window-major (coalesced window stores) -------
#define HSTR 40

__global__ __launch_bounds__(256) void dwconv_kernel(
    const float* __restrict__ qkv1,     // [b][1152][hw]
    const float* __restrict__ dww,      // [1152][9]
    float* __restrict__ gwin)
{
    __shared__ __align__(16) float h6[6][34 * HSTR];
    __shared__ float s_dww[144 * 9];
    __shared__ __align__(8) uint64_t mbar[3];

    const int tid  = threadIdx.x;
    const int tile = blockIdx.x;           // 0..63
    const int head = blockIdx.y;
    const int b    = blockIdx.z;
    const int tyb = tile >> 3, txb = tile & 7;
    const int y0 = tyb * 32 - 1, x0 = txb * 32 - 1;

    const int cs = x0 - 3;
    const int src_off = cs < 0 ? 0 : cs;
    const int dst_off = src_off - cs;
    const int cend = (cs + 40 > 256) ? 256 : (cs + 40);
    const uint32_t rowbytes = (uint32_t)(cend - src_off) * 4;
    const int r_lo = (y0 < 0) ? 1 : 0;
    const int r_hi = (y0 + 33 > 255) ? 32 : 33;
    const uint32_t expect2 = 2u * (uint32_t)(r_hi - r_lo + 1) * rowbytes;

    for (int e = tid; e < 144 * 9; e += 256) {
        const int l = e / 9, kk = e - l * 9;
        const int z = l / 48, cl = l - z * 48;
        s_dww[e] = dww[(size_t)(z * DIMC + head * CPH + cl) * 9 + kk];
    }
    for (int e = tid; e < 6 * 34 * HSTR; e += 256) (&h6[0][0])[e] = 0.f;
    if (tid < 3) MBARRIER_INIT(smem_u32(&mbar[tid]), 1);
    __syncthreads();
    FENCE_PROXY_ASYNC();

    const size_t bbase = (size_t)b * QKV_M * HW;
    const int wid = tid >> 5, lane = tid & 31;

    auto issue = [&](int s) {
        const int slot = s % 3;
        const uint32_t mb = smem_u32(&mbar[slot]);
        if (lane == 0) MBARRIER_EXPECT_TX(mb, expect2);
        for (int i = lane; i < 68; i += 32) {
            const int sub = i / 34;
            const int r = i - sub * 34;
            if (r < r_lo || r > r_hi) continue;
            const int ch = 2 * s + sub;
            const int gc = (ch / 48) * DIMC + head * CPH + (ch % 48);
            const float* srcc = qkv1 + bbase + (size_t)gc * HW;
            BULK_CPY(smem_u32(&h6[slot * 2 + sub][0]) + (uint32_t)(r * HSTR + dst_off) * 4,
                     srcc + (size_t)(y0 + r) * 256 + src_off, rowbytes, mb);
        }
    };
    if (wid == 0) { issue(0); issue(1); }

    // coalesced output mapping: 16 threads per window, contiguous 256B runs
    const int wl = tid >> 4;
    const int e0 = (tid & 15) * 4;
    const int wy_l = wl >> 2, wx_l = wl & 3;
    const int orow = wy_l * 8 + (e0 >> 3);
    const int xq   = wx_l * 8 + (e0 & 7);
    const int win = (tyb * 4 + wy_l) * 32 + txb * 4 + wx_l;
    float* wbase = gwin + (((size_t)(b * HEADS + head) * 1024 + win) * 144) * 64 + e0;

#pragma unroll 1
    for (int s = 0; s < 72; s++) {
        if (wid == 0 && s + 2 < 72) issue(s + 2);
        MBARRIER_WAIT_PARITY(smem_u32(&mbar[s % 3]), (s / 3) & 1);

#pragma unroll
        for (int sub = 0; sub < 2; sub++) {
            const int ch = 2 * s + sub;
            const float* hb = h6[(s % 3) * 2 + sub] + orow * HSTR + xq + 3;
            const float* wp = s_dww + ch * 9;
            float w[9];
#pragma unroll
            for (int i = 0; i < 9; i++) w[i] = wp[i];
            float a[3][6];
#pragma unroll
            for (int dy = 0; dy < 3; dy++)
#pragma unroll
                for (int c = 0; c < 6; c++) a[dy][c] = hb[dy * HSTR + c];
            float4 o;
            o.x = a[0][0]*w[0] + a[0][1]*w[1] + a[0][2]*w[2]
                + a[1][0]*w[3] + a[1][1]*w[4] + a[1][2]*w[5]
                + a[2][0]*w[6] + a[2][1]*w[7] + a[2][2]*w[8];
            o.y = a[0][1]*w[0] + a[0][2]*w[1] + a[0][3]*w[2]
                + a[1][1]*w[3] + a[1][2]*w[4] + a[1][3]*w[5]
                + a[2][1]*w[6] + a[2][2]*w[7] + a[2][3]*w[8];
            o.z = a[0][2]*w[0] + a[0][3]*w[1] + a[0][4]*w[2]
                + a[1][2]*w[3] + a[1][3]*w[4] + a[1][4]*w[5]
                + a[2][2]*w[6] + a[2][3]*w[7] + a[2][4]*w[8];
            o.w = a[0][3]*w[0] + a[0][4]*w[1] + a[0][5]*w[2]
                + a[1][3]*w[3] + a[1][4]*w[4] + a[1][5]*w[5]
                + a[2][3]*w[6] + a[2][4]*w[7] + a[2][5]*w[8];
            *reinterpret_cast<float4*>(wbase + (size_t)ch * 64) = o;
        }
        __syncthreads();
    }
}

// ---------------- window channel-attention (low-smem, 4 CTAs/SM) -------------
#define SQ 68
#define S_ATTN_STRIDE 50
#define AT_OFF   3264
#define QKB_OFF  22656
#define QKB_SZ   6144
#define A_SMEM_BYTES (QKB_OFF + 4 * QKB_SZ)    // 47232

__global__ __launch_bounds__(256) void attn_kernel(
    const float* __restrict__ gwin,          // [(b*8+head)*1024+win][144][64]
    const float* __restrict__ temperature,
    __nv_bfloat16* __restrict__ out_hi,      // [b][hw][384]
    __nv_bfloat16* __restrict__ out_lo)
{
    extern __shared__ float sm[];
    float* s_v    = sm;                      // 48 x SQ (v rows)
    float* s_attn = sm + AT_OFF;             // 48 x 50
    __shared__ __align__(8) uint64_t a_mbar;
    const uint32_t smb = smem_u32(sm);
    const uint32_t qh_b = smb + QKB_OFF;
    const uint32_t kh_b = smb + QKB_OFF + 2 * QKB_SZ;
    char* smc = reinterpret_cast<char*>(sm);

    const int tid  = threadIdx.x;
    const int win  = blockIdx.x;
    const int head = blockIdx.y;
    const int b    = blockIdx.z;
    const int wy = win >> 5, wx = win & 31;
    const int wid = tid >> 5, lane = tid & 31;

    if (tid == 0) MBARRIER_INIT(smem_u32(&a_mbar), 1);
    __syncthreads();

    const float* base = gwin + (((size_t)(b * HEADS + head) * 1024 + win) * 144) * 64;

    if (tid < 32) {
        const uint32_t mb = smem_u32(&a_mbar);
        if (tid == 0) MBARRIER_EXPECT_TX(mb, 48 * 256);
        for (int r = tid; r < 48; r += 32)
            BULK_CPY(smb + (uint32_t)(r * SQ) * 4, base + (size_t)(96 + r) * 64, 256, mb);
    }

    const float temp = __ldg(&temperature[head]);

    // ---- L2 normalize q,k straight from GLOBAL; emit bf16 hi/lo swizzled ----
    {
        const int grp = tid >> 3;
        const int gl  = tid & 7;
#pragma unroll
        for (int it = 0; it < 3; it++) {
            const int r = grp + it * 32;
            const float* gp = base + (size_t)r * 64 + gl * 8;
            float4 v0 = *reinterpret_cast<const float4*>(gp);
            float4 v1 = *reinterpret_cast<const float4*>(gp + 4);
            float s = v0.x * v0.x + v0.y * v0.y + v0.z * v0.z + v0.w * v0.w
                    + v1.x * v1.x + v1.y * v1.y + v1.z * v1.z + v1.w * v1.w;
            s += __shfl_xor_sync(0xffffffffu, s, 1);
            s += __shfl_xor_sync(0xffffffffu, s, 2);
            s += __shfl_xor_sync(0xffffffffu, s, 4);
            const float inv = 1.f / fmaxf(sqrtf(s), 1e-12f);
            float f[8] = { v0.x * inv, v0.y * inv, v0.z * inv, v0.w * inv,
                           v1.x * inv, v1.y * inv, v1.z * inv, v1.w * inv };
            uint32_t hi[4], lo[4];
#pragma unroll
            for (int p = 0; p < 4; p++) {
                __nv_bfloat162 h2 = __floats2bfloat162_rn(f[2 * p], f[2 * p + 1]);
                hi[p] = *reinterpret_cast<uint32_t*>(&h2);
                __nv_bfloat162 l2 = __floats2bfloat162_rn(
                    f[2 * p]     - __bfloat162float(h2.x),
                    f[2 * p + 1] - __bfloat162float(h2.y));
                lo[p] = *reinterpret_cast<uint32_t*>(&l2);
            }
            const int rr = (r < 48) ? r : r - 48;
            const uint32_t bh = ((r < 48) ? (QKB_OFF) : (QKB_OFF + 2 * QKB_SZ)) + swz128r(rr, gl);
            *reinterpret_cast<uint4*>(smc + bh) = make_uint4(hi[0], hi[1], hi[2], hi[3]);
            *reinterpret_cast<uint4*>(smc + bh + QKB_SZ) = make_uint4(lo[0], lo[1], lo[2], lo[3]);
        }
    }
    __syncthreads();

    // ---- QK via HMMA: attn[48][48] = Q . K^T (3-term hi/lo), 6 warps ----
    if (wid < 6) {
        const int wm = (wid >> 1) * 16;
        const int wn = (wid & 1) * 24;
        float acc[3][4];
#pragma unroll
        for (int j = 0; j < 3; j++)
#pragma unroll
            for (int k = 0; k < 4; k++) acc[j][k] = 0.f;

        const int a_r  = wm + (lane & 7) + ((lane >> 3) & 1) * 8;
        const int a_cb = lane >> 4;
        const int b_r  = wn + (lane & 7) + ((lane >> 4) & 1) * 8;
        const int b_cb = (lane >> 3) & 1;
        const int b2_r = wn + 16 + (lane & 7);

#pragma unroll
        for (int k16 = 0; k16 < 4; k16++) {
            uint32_t ah[4], al[4], b4h[4], b4l[4], b2h[2], b2l[2];
            const uint32_t qa = qh_b + swz128r(a_r, k16 * 2 + a_cb);
            ldmx4(ah, qa); ldmx4(al, qa + QKB_SZ);
            const uint32_t ka = kh_b + swz128r(b_r, k16 * 2 + b_cb);
            ldmx4(b4h, ka); ldmx4(b4l, ka + QKB_SZ);
            const uint32_t k2 = kh_b + swz128r(b2_r, k16 * 2 + b_cb);
            ldmx2(b2h, k2); ldmx2(b2l, k2 + QKB_SZ);

            mma16816(acc[0], ah, b4h[0], b4h[1]);
            mma16816(acc[1], ah, b4h[2], b4h[3]);
            mma16816(acc[2], ah, b2h[0], b2h[1]);
            mma16816(acc[0], ah, b4l[0], b4l[1]);
            mma16816(acc[1], ah, b4l[2], b4l[3]);
            mma16816(acc[2], ah, b2l[0], b2l[1]);
            mma16816(acc[0], al, b4h[0], b4h[1]);
            mma16816(acc[1], al, b4h[2], b4h[3]);
            mma16816(acc[2], al, b2h[0], b2h[1]);
        }
        const int row = wm + (lane >> 2);
        const int colb = wn + (lane & 3) * 2;
#pragma unroll
        for (int j = 0; j < 3; j++) {
            const int col = colb + j * 8;
            *reinterpret_cast<float2*>(&s_attn[row * S_ATTN_STRIDE + col]) =
                make_float2(acc[j][0] * temp, acc[j][1] * temp);
            *reinterpret_cast<float2*>(&s_attn[(row + 8) * S_ATTN_STRIDE + col]) =
                make_float2(acc[j][2] * temp, acc[j][3] * temp);
        }
    }
    __syncthreads();

    // ---- softmax over d ----
    {
        for (int r = wid; r < 48; r += 8) {
            const float v0 = s_attn[r * S_ATTN_STRIDE + lane];
            const float v1 = (lane < 16) ? s_attn[r * S_ATTN_STRIDE + lane + 32] : -1e30f;
            float m = fmaxf(v0, v1);
#pragma unroll
            for (int off = 16; off; off >>= 1) m = fmaxf(m, __shfl_xor_sync(0xffffffffu, m, off));
            const float e0 = __expf(v0 - m);
            const float e1 = (lane < 16) ? __expf(v1 - m) : 0.f;
            float s = e0 + e1;
#pragma unroll
            for (int off = 16; off; off >>= 1) s += __shfl_xor_sync(0xffffffffu, s, off);
            const float inv = 1.f / s;
            s_attn[r * S_ATTN_STRIDE + lane] = e0 * inv;
            if (lane < 16) s_attn[r * S_ATTN_STRIDE + lane + 32] = e1 * inv;
        }
    }
    __syncthreads();

    MBARRIER_WAIT_PARITY(smem_u32(&a_mbar), 0);

    // ---- out[c][n] = sum_d attn[c][d] * v[d][n]; out overwrites qk bf16 ----
    float* s_out = reinterpret_cast<float*>(smc + QKB_OFF);
    {
        const int ty = tid >> 4, tx = tid & 15;
        float4 a0c = make_float4(0.f, 0.f, 0.f, 0.f);
        float4 a1c = a0c, a2c = a0c;
        const float* ar0 = s_attn + (ty * 3 + 0) * S_ATTN_STRIDE;
        const float* ar1 = s_attn + (ty * 3 + 1) * S_ATTN_STRIDE;
        const float* ar2 = s_attn + (ty * 3 + 2) * S_ATTN_STRIDE;
#pragma unroll 4
        for (int d = 0; d < 48; ++d) {
            const float a0 = ar0[d], a1 = ar1[d], a2 = ar2[d];
            const float4 v = *reinterpret_cast<const float4*>(&s_v[d * SQ + tx * 4]);
            a0c.x += a0 * v.x; a0c.y += a0 * v.y; a0c.z += a0 * v.z; a0c.w += a0 * v.w;
            a1c.x += a1 * v.x; a1c.y += a1 * v.y; a1c.z += a1 * v.z; a1c.w += a1 * v.w;
            a2c.x += a2 * v.x; a2c.y += a2 * v.y; a2c.z += a2 * v.z; a2c.w += a2 * v.w;
        }
        *reinterpret_cast<float4*>(&s_out[(ty * 3 + 0) * SQ + tx * 4]) = a0c;
        *reinterpret_cast<float4*>(&s_out[(ty * 3 + 1) * SQ + tx * 4]) = a1c;
        *reinterpret_cast<float4*>(&s_out[(ty * 3 + 2) * SQ + tx * 4]) = a2c;
    }
    __syncthreads();

    // ---- write bf16 hi/lo to [b][hw][384] ----
    for (int e = tid; e < 1536; e += 256) {
        const int c2 = e % 24;
        const int n  = e / 24;
        const int c  = c2 * 2;
        const float va = s_out[c * SQ + n];
        const float vb = s_out[(c + 1) * SQ + n];
        const int yy = n >> 3, xx = n & 7;
        const int hw = ((wy * 8 + yy) << 8) + wx * 8 + xx;
        const size_t off = ((size_t)b * HW + hw) * DIMC + head * CPH + c;
        const __nv_bfloat16 ha = __float2bfloat16(va);
        const __nv_bfloat16 hb = __float2bfloat16(vb);
        __nv_bfloat162 hi2, lo2;
        hi2.x = ha; hi2.y = hb;
        lo2.x = __float2bfloat16(va - __bfloat162float(ha));
        lo2.y = __float2bfloat16(vb - __bfloat162float(hb));
        *reinterpret_cast<__nv_bfloat162*>(&out_hi[off]) = hi2;
        *reinterpret_cast<__nv_bfloat162*>(&out_lo[off]) = lo2;
    }
}

// ---------------- launch ----------------------------------------------------
extern "C" void kernel_launch(void* const* d_in, const int* in_sizes, int n_in,
                              void* d_out, int out_size)
{
    const float* x      = (const float*)d_in[0];
    const float* qkv_w  = (const float*)d_in[1];
    const float* dw_w   = (const float*)d_in[2];
    const float* temp   = (const float*)d_in[3];
    const float* proj_w = (const float*)d_in[4];
    const float* proj_b = (const float*)d_in[5];
    float* out = (float*)d_out;

    float *qkv_buf, *win_buf;
    __half *xt_h, *wq_h;
    __nv_bfloat16 *at_hi, *at_lo, *wp_hi, *wp_lo;
    cudaGetSymbolAddress((void**)&qkv_buf, g_qkv);
    cudaGetSymbolAddress((void**)&win_buf, g_win);
    cudaGetSymbolAddress((void**)&xt_h, g_xt_h);
    cudaGetSymbolAddress((void**)&wq_h, g_wq_h);
    cudaGetSymbolAddress((void**)&at_hi, g_at_hi);
    cudaGetSymbolAddress((void**)&at_lo, g_at_lo);
    cudaGetSymbolAddress((void**)&wp_hi, g_wp_hi);
    cudaGetSymbolAddress((void**)&wp_lo, g_wp_lo);

    cudaFuncSetAttribute(attn_kernel, cudaFuncAttributeMaxDynamicSharedMemorySize, A_SMEM_BYTES);
    cudaFuncSetAttribute(hmma_gemm_f16, cudaFuncAttributeMaxDynamicSharedMemorySize, HG1_SMEM);
    cudaFuncSetAttribute(hmma_gemm, cudaFuncAttributeMaxDynamicSharedMemorySize, HG_SMEM);

    // weight prep
    conv_w_h<<<(QKV_M * DIMC + 255) / 256, 256>>>(qkv_w, wq_h, QKV_M * DIMC);
    split_w<<<(DIMC * DIMC + 255) / 256, 256>>>(proj_w, wp_hi, wp_lo, DIMC * DIMC);

    // x -> transposed fp16 [b][hw][384]
    transpose_h<<<dim3(HW / 32, DIMC / 32, BATCH), 256>>>(x, xt_h, DIMC, HW);

    // qkv = W_qkv . x   (fp16 single-pass) -> g_qkv f32
    hmma_gemm_f16<<<dim3(QKV_M / 128, HW / 128, BATCH), 256, HG1_SMEM>>>(
        wq_h, xt_h, qkv_buf, QKV_M, HW, DIMC);

    // depthwise 3x3 -> window-major layout
    dwconv_kernel<<<dim3(64, HEADS, BATCH), 256>>>(qkv_buf, dw_w, win_buf);

    // window channel attention -> bf16 hi/lo [b][hw][384]
    attn_kernel<<<dim3(1024, HEADS, BATCH), 256, A_SMEM_BYTES>>>(
        win_buf, temp, at_hi, at_lo);

    // out = W_proj . att + b  (bf16 3-term, full accuracy)
    hmma_gemm<<<dim3(DIMC / 128, HW / 128, BATCH), 256, HG_SMEM>>>(
        wp_hi, wp_lo, at_hi, at_lo, out, DIMC, HW, DIMC, proj_b);
}

// round 16
// speedup vs baseline: 1.6199x; 1.1520x over previous
#include <cuda_runtime.h>
#include <cuda_fp16.h>
#include <cstdint>
#include <math.h>

// Problem constants
#define DIMC   384
#define HEADS  8
#define CPH    48
#define HH     256
#define WW     256
#define HW     65536
#define BATCH  2
#define QKV_M  1152        // 3*dim

// ---------------- scratch (device globals) ----------------------------------
__device__ float g_qkv[(size_t)BATCH * QKV_M * HW];           // [b][1152][hw] f32
__device__ float g_win[(size_t)BATCH * HEADS * 1024 * 144 * 64]; // window-major dwconv out
__device__ __half g_xt_h[(size_t)BATCH * HW * DIMC];          // [b][hw][384] fp16
__device__ __half g_at_h[(size_t)BATCH * HW * DIMC];          // attention out fp16
__device__ __half g_wq_h[QKV_M * DIMC];
__device__ __half g_wp_h[DIMC * DIMC];

// ---------------- helpers ----------------------------------------------------
__device__ __forceinline__ uint32_t smem_u32(const void* p) {
    uint32_t a;
    asm("{ .reg .u64 t; cvta.to.shared.u64 t, %1; cvt.u32.u64 %0, t; }" : "=r"(a) : "l"(p));
    return a;
}
#define CP_ASYNC16(saddr, gptr) \
    asm volatile("cp.async.cg.shared.global [%0], [%1], 16;" :: "r"(saddr), "l"(gptr))
#define CP_COMMIT() asm volatile("cp.async.commit_group;" ::: "memory")
#define CP_WAIT0()  asm volatile("cp.async.wait_group 0;" ::: "memory")
#define CP_WAIT1()  asm volatile("cp.async.wait_group 1;" ::: "memory")

#define MBARRIER_INIT(addr, cnt) \
    asm volatile("mbarrier.init.shared.b64 [%0], %1;" :: "r"((uint32_t)(addr)), "r"((uint32_t)(cnt)) : "memory")
#define MBARRIER_EXPECT_TX(addr, bytes) \
    asm volatile("mbarrier.arrive.expect_tx.shared.b64 _, [%0], %1;" :: "r"((uint32_t)(addr)), "r"((uint32_t)(bytes)) : "memory")
#define MBARRIER_WAIT_PARITY(mbar_addr, parity) do { \
    uint32_t _mbar = (uint32_t)(mbar_addr); \
    uint32_t _par = (uint32_t)(parity); \
    uint32_t _done; \
    asm volatile( \
        "{\n\t.reg .pred p;\n\t" \
        "mbarrier.try_wait.parity.shared.b64 p, [%1], %2;\n\t" \
        "selp.b32 %0, 1, 0, p;\n\t}" \
        : "=r"(_done) : "r"(_mbar), "r"(_par) : "memory"); \
    if (!_done) { \
        asm volatile( \
            "{\n\t.reg .pred P1;\n\t" \
            "WL_%=:\n\t" \
            "mbarrier.try_wait.parity.shared.b64 P1, [%0], %1;\n\t" \
            "@P1 bra.uni WD_%=;\n\t" \
            "bra.uni WL_%=;\n\t" \
            "WD_%=:\n\t}" \
            :: "r"(_mbar), "r"(_par) : "memory"); \
    } \
} while (0)
#define BULK_CPY(dst_smem, gsrc, bytes, mbar) \
    asm volatile("cp.async.bulk.shared::cta.global.mbarrier::complete_tx::bytes [%0], [%1], %2, [%3];" \
                 :: "r"((uint32_t)(dst_smem)), "l"(gsrc), "r"((uint32_t)(bytes)), "r"((uint32_t)(mbar)) : "memory")
#define FENCE_PROXY_ASYNC() asm volatile("fence.proxy.async.shared::cta;" ::: "memory")

__device__ __forceinline__ void ldmx4(uint32_t* d, uint32_t addr) {
    asm volatile("ldmatrix.sync.aligned.m8n8.x4.shared.b16 {%0,%1,%2,%3}, [%4];"
                 : "=r"(d[0]), "=r"(d[1]), "=r"(d[2]), "=r"(d[3]) : "r"(addr));
}
__device__ __forceinline__ void ldmx2(uint32_t* d, uint32_t addr) {
    asm volatile("ldmatrix.sync.aligned.m8n8.x2.shared.b16 {%0,%1}, [%2];"
                 : "=r"(d[0]), "=r"(d[1]) : "r"(addr));
}
__device__ __forceinline__ void mma16816h(float* c, const uint32_t* a, uint32_t b0, uint32_t b1) {
    asm volatile("mma.sync.aligned.m16n8k16.row.col.f32.f16.f16.f32 "
                 "{%0,%1,%2,%3}, {%4,%5,%6,%7}, {%8,%9}, {%0,%1,%2,%3};"
                 : "+f"(c[0]), "+f"(c[1]), "+f"(c[2]), "+f"(c[3])
                 : "r"(a[0]), "r"(a[1]), "r"(a[2]), "r"(a[3]), "r"(b0), "r"(b1));
}
__device__ __forceinline__ uint32_t swz(int r, int cb) {          // 64B rows (GEMM tiles)
    return (uint32_t)(r * 64 + ((cb ^ ((r >> 1) & 3)) << 4));
}
__device__ __forceinline__ uint32_t swz128r(int r, int cb) {      // 128B rows (attn fp16)
    return (uint32_t)(r * 128 + ((cb ^ (r & 7)) << 4));
}

// ---------------- transpose to fp16 ------------------------------------------
__global__ __launch_bounds__(256) void transpose_h(
    const float* __restrict__ in, __half* __restrict__ outp, int C, int N)
{
    __shared__ float t[32][33];
    const int n0 = blockIdx.x * 32, c0 = blockIdx.y * 32;
    const size_t base = (size_t)blockIdx.z * C * N;
    const int tx = threadIdx.x & 31, ty = threadIdx.x >> 5;
#pragma unroll
    for (int i = 0; i < 4; i++) {
        const int c = ty + i * 8;
        t[c][tx] = in[base + (size_t)(c0 + c) * N + n0 + tx];
    }
    __syncthreads();
#pragma unroll
    for (int i = 0; i < 4; i++) {
        const int n = ty + i * 8;
        outp[base + (size_t)(n0 + n) * C + c0 + tx] = __float2half(t[tx][n]);
    }
}

__global__ void conv_w_h(const float* __restrict__ w, __half* __restrict__ outp, int n)
{
    const int i = blockIdx.x * 256 + threadIdx.x;
    if (i < n) outp[i] = __float2half(w[i]);
}

// ---------------- fp16 single-pass GEMM: C = A . B^T (+bias) ----------------
// A [M][K] fp16, B per-batch [N][K] fp16, C [M][N] f32.
// CTA tile 128x128, K-stage 32, 3-stage ring; stage = A 8K + B 8K = 16K.
#define HG1_SMEM 49152

template <int WITH_BIAS>
__global__ __launch_bounds__(256) void hmma_gemm_f16(
    const __half* __restrict__ Ag, const __half* __restrict__ Bg,
    float* __restrict__ Cg, int M, int N, int K, const float* __restrict__ bias)
{
    extern __shared__ char smem[];
    const uint32_t sb = smem_u32(smem);
    const int tid = threadIdx.x;
    const int wid = tid >> 5, lane = tid & 31;
    const int bM = blockIdx.x * 128;
    const int bN = blockIdx.y * 128;
    const size_t bb = (size_t)blockIdx.z * (size_t)N * K;
    float* Cp = Cg + (size_t)blockIdx.z * (size_t)M * N;

    const __half* A = Ag + (size_t)bM * K;
    const __half* B = Bg + bb + (size_t)bN * K;

    const int cb = tid & 3;
    const int r0 = tid >> 2;      // 0..63
    const int nst = K / 32;       // 12

#pragma unroll
    for (int ps = 0; ps < 2; ps++) {
        const uint32_t st = sb + ps * 16384;
        const int kk = ps * 32 + cb * 8;
#pragma unroll
        for (int i = 0; i < 2; i++) {
            const int r = r0 + i * 64;
            const uint32_t so = swz(r, cb);
            CP_ASYNC16(st + so,        A + (size_t)r * K + kk);
            CP_ASYNC16(st + 8192 + so, B + (size_t)r * K + kk);
        }
        CP_COMMIT();
    }

    float acc[4][4][4];
#pragma unroll
    for (int i = 0; i < 4; i++)
#pragma unroll
        for (int j = 0; j < 4; j++)
#pragma unroll
            for (int k = 0; k < 4; k++) acc[i][j][k] = 0.f;

    const int wm = (wid >> 2) * 64;
    const int wn = (wid & 3) * 32;
    const int a_rbase = wm + ((lane >> 3) & 1) * 8 + (lane & 7);
    const int a_cbad  = lane >> 4;
    const int b_rbase = wn + ((lane >> 4) & 1) * 8 + (lane & 7);
    const int b_cbad  = (lane >> 3) & 1;

    int sidx = 0;
    for (int s = 0; s < nst; s++) {
        if (s + 1 < nst) CP_WAIT1(); else CP_WAIT0();
        __syncthreads();

        if (s + 2 < nst) {
            int fi = sidx + 2; if (fi >= 3) fi -= 3;
            const uint32_t st = sb + fi * 16384;
            const int kk = (s + 2) * 32 + cb * 8;
#pragma unroll
            for (int i = 0; i < 2; i++) {
                const int r = r0 + i * 64;
                const uint32_t so = swz(r, cb);
                CP_ASYNC16(st + so,        A + (size_t)r * K + kk);
                CP_ASYNC16(st + 8192 + so, B + (size_t)r * K + kk);
            }
            CP_COMMIT();
        }

        const uint32_t st = sb + sidx * 16384;
#pragma unroll
        for (int k16 = 0; k16 < 2; k16++) {
            uint32_t bf[2][4];
#pragma unroll
            for (int nh = 0; nh < 2; nh++)
                ldmx4(bf[nh], st + 8192 + swz(b_rbase + nh * 16, k16 * 2 + b_cbad));
#pragma unroll
            for (int mh = 0; mh < 4; mh++) {
                uint32_t af[4];
                ldmx4(af, st + swz(a_rbase + mh * 16, k16 * 2 + a_cbad));
#pragma unroll
                for (int nb = 0; nb < 4; nb++) {
                    const uint32_t* f = &bf[nb >> 1][(nb & 1) * 2];
                    mma16816h(acc[mh][nb], af, f[0], f[1]);
                }
            }
        }
        if (++sidx == 3) sidx = 0;
    }
    __syncthreads();

    const int row0 = bM + wm + (lane >> 2);
    const int col0 = bN + wn + (lane & 3) * 2;
#pragma unroll
    for (int mh = 0; mh < 4; mh++) {
#pragma unroll
        for (int p = 0; p < 2; p++) {
            const int row = row0 + mh * 16 + p * 8;
            const float bi = WITH_BIAS ? __ldg(&bias[row]) : 0.f;
#pragma unroll
            for (int nb = 0; nb < 4; nb++) {
                float2 v;
                v.x = acc[mh][nb][p * 2 + 0] + bi;
                v.y = acc[mh][nb][p * 2 + 1] + bi;
                *reinterpret_cast<float2*>(&Cp[(size_t)row * N + col0 + nb * 8]) = v;
            }
        }
    }
}

// ---------------- dwconv 3x3 -> window-major (coalesced window stores) -------
#define HSTR 40

__global__ __launch_bounds__(256) void dwconv_kernel(
    const float* __restrict__ qkv1,     // [b][1152][hw]
    const float* __restrict__ dww,      // [1152][9]
    float* __restrict__ gwin)
{
    __shared__ __align__(16) float h6[6][34 * HSTR];
    __shared__ float s_dww[144 * 9];
    __shared__ __align__(8) uint64_t mbar[3];

    const int tid  = threadIdx.x;
    const int tile = blockIdx.x;           // 0..63
    const int head = blockIdx.y;
    const int b    = blockIdx.z;
    const int tyb = tile >> 3, txb = tile & 7;
    const int y0 = tyb * 32 - 1, x0 = txb * 32 - 1;

    const int cs = x0 - 3;
    const int src_off = cs < 0 ? 0 : cs;
    const int dst_off = src_off - cs;
    const int cend = (cs + 40 > 256) ? 256 : (cs + 40);
    const uint32_t rowbytes = (uint32_t)(cend - src_off) * 4;
    const int r_lo = (y0 < 0) ? 1 : 0;
    const int r_hi = (y0 + 33 > 255) ? 32 : 33;
    const uint32_t expect2 = 2u * (uint32_t)(r_hi - r_lo + 1) * rowbytes;

    for (int e = tid; e < 144 * 9; e += 256) {
        const int l = e / 9, kk = e - l * 9;
        const int z = l / 48, cl = l - z * 48;
        s_dww[e] = dww[(size_t)(z * DIMC + head * CPH + cl) * 9 + kk];
    }
    for (int e = tid; e < 6 * 34 * HSTR; e += 256) (&h6[0][0])[e] = 0.f;
    if (tid < 3) MBARRIER_INIT(smem_u32(&mbar[tid]), 1);
    __syncthreads();
    FENCE_PROXY_ASYNC();

    const size_t bbase = (size_t)b * QKV_M * HW;
    const int wid = tid >> 5, lane = tid & 31;

    auto issue = [&](int s) {
        const int slot = s % 3;
        const uint32_t mb = smem_u32(&mbar[slot]);
        if (lane == 0) MBARRIER_EXPECT_TX(mb, expect2);
        for (int i = lane; i < 68; i += 32) {
            const int sub = i / 34;
            const int r = i - sub * 34;
            if (r < r_lo || r > r_hi) continue;
            const int ch = 2 * s + sub;
            const int gc = (ch / 48) * DIMC + head * CPH + (ch % 48);
            const float* srcc = qkv1 + bbase + (size_t)gc * HW;
            BULK_CPY(smem_u32(&h6[slot * 2 + sub][0]) + (uint32_t)(r * HSTR + dst_off) * 4,
                     srcc + (size_t)(y0 + r) * 256 + src_off, rowbytes, mb);
        }
    };
    if (wid == 0) { issue(0); issue(1); }

    const int wl = tid >> 4;
    const int e0 = (tid & 15) * 4;
    const int wy_l = wl >> 2, wx_l = wl & 3;
    const int orow = wy_l * 8 + (e0 >> 3);
    const int xq   = wx_l * 8 + (e0 & 7);
    const int win = (tyb * 4 + wy_l) * 32 + txb * 4 + wx_l;
    float* wbase = gwin + (((size_t)(b * HEADS + head) * 1024 + win) * 144) * 64 + e0;

#pragma unroll 1
    for (int s = 0; s < 72; s++) {
        if (wid == 0 && s + 2 < 72) issue(s + 2);
        MBARRIER_WAIT_PARITY(smem_u32(&mbar[s % 3]), (s / 3) & 1);

#pragma unroll
        for (int sub = 0; sub < 2; sub++) {
            const int ch = 2 * s + sub;
            const float* hb = h6[(s % 3) * 2 + sub] + orow * HSTR + xq + 3;
            const float* wp = s_dww + ch * 9;
            float w[9];
#pragma unroll
            for (int i = 0; i < 9; i++) w[i] = wp[i];
            float a[3][6];
#pragma unroll
            for (int dy = 0; dy < 3; dy++)
#pragma unroll
                for (int c = 0; c < 6; c++) a[dy][c] = hb[dy * HSTR + c];
            float4 o;
            o.x = a[0][0]*w[0] + a[0][1]*w[1] + a[0][2]*w[2]
                + a[1][0]*w[3] + a[1][1]*w[4] + a[1][2]*w[5]
                + a[2][0]*w[6] + a[2][1]*w[7] + a[2][2]*w[8];
            o.y = a[0][1]*w[0] + a[0][2]*w[1] + a[0][3]*w[2]
                + a[1][1]*w[3] + a[1][2]*w[4] + a[1][3]*w[5]
                + a[2][1]*w[6] + a[2][2]*w[7] + a[2][3]*w[8];
            o.z = a[0][2]*w[0] + a[0][3]*w[1] + a[0][4]*w[2]
                + a[1][2]*w[3] + a[1][3]*w[4] + a[1][4]*w[5]
                + a[2][2]*w[6] + a[2][3]*w[7] + a[2][4]*w[8];
            o.w = a[0][3]*w[0] + a[0][4]*w[1] + a[0][5]*w[2]
                + a[1][3]*w[3] + a[1][4]*w[4] + a[1][5]*w[5]
                + a[2][3]*w[6] + a[2][4]*w[7] + a[2][5]*w[8];
            *reinterpret_cast<float4*>(wbase + (size_t)ch * 64) = o;
        }
        __syncthreads();
    }
}

// ---------------- window channel-attention (fp16 path) -----------------------
// smem: s_v f32 [48][68] @0 (13056 B) | s_attn f32 [48][50] @13056 (9600 B)
//       | q fp16 [48][64] @22656 | k fp16 @28800 | (s_out f32 overlays @22656)
#define SQ 68
#define S_ATTN_STRIDE 50
#define AT_OFF   3264                          // floats
#define QKB_OFF  22656                         // bytes
#define QKB_SZ   6144
#define A_SMEM_BYTES (QKB_OFF + 13056)         // 35712 (covers qk 12288 & s_out 13056)

__global__ __launch_bounds__(256) void attn_kernel(
    const float* __restrict__ gwin,          // [(b*8+head)*1024+win][144][64]
    const float* __restrict__ temperature,
    __half* __restrict__ out_h)              // [b][hw][384] fp16
{
    extern __shared__ float sm[];
    float* s_v    = sm;                      // 48 x SQ
    float* s_attn = sm + AT_OFF;             // 48 x 50
    __shared__ __align__(8) uint64_t a_mbar;
    const uint32_t smb = smem_u32(sm);
    const uint32_t qh_b = smb + QKB_OFF;                 // q fp16
    const uint32_t kh_b = smb + QKB_OFF + QKB_SZ;        // k fp16
    char* smc = reinterpret_cast<char*>(sm);

    const int tid  = threadIdx.x;
    const int win  = blockIdx.x;
    const int head = blockIdx.y;
    const int b    = blockIdx.z;
    const int wy = win >> 5, wx = win & 31;
    const int wid = tid >> 5, lane = tid & 31;

    if (tid == 0) MBARRIER_INIT(smem_u32(&a_mbar), 1);
    __syncthreads();

    const float* base = gwin + (((size_t)(b * HEADS + head) * 1024 + win) * 144) * 64;

    // ---- bulk-copy v (rows 96..143) ----
    if (tid < 32) {
        const uint32_t mb = smem_u32(&a_mbar);
        if (tid == 0) MBARRIER_EXPECT_TX(mb, 48 * 256);
        for (int r = tid; r < 48; r += 32)
            BULK_CPY(smb + (uint32_t)(r * SQ) * 4, base + (size_t)(96 + r) * 64, 256, mb);
    }

    const float temp = __ldg(&temperature[head]);

    // ---- L2 normalize q,k from GLOBAL; emit fp16 (swizzled 128B rows) ----
    {
        const int grp = tid >> 3;
        const int gl  = tid & 7;
#pragma unroll
        for (int it = 0; it < 3; it++) {
            const int r = grp + it * 32;     // 0..95
            const float* gp = base + (size_t)r * 64 + gl * 8;
            float4 v0 = *reinterpret_cast<const float4*>(gp);
            float4 v1 = *reinterpret_cast<const float4*>(gp + 4);
            float s = v0.x * v0.x + v0.y * v0.y + v0.z * v0.z + v0.w * v0.w
                    + v1.x * v1.x + v1.y * v1.y + v1.z * v1.z + v1.w * v1.w;
            s += __shfl_xor_sync(0xffffffffu, s, 1);
            s += __shfl_xor_sync(0xffffffffu, s, 2);
            s += __shfl_xor_sync(0xffffffffu, s, 4);
            const float inv = 1.f / fmaxf(sqrtf(s), 1e-12f);
            __half2 h[4];
            h[0] = __floats2half2_rn(v0.x * inv, v0.y * inv);
            h[1] = __floats2half2_rn(v0.z * inv, v0.w * inv);
            h[2] = __floats2half2_rn(v1.x * inv, v1.y * inv);
            h[3] = __floats2half2_rn(v1.z * inv, v1.w * inv);
            const int rr = (r < 48) ? r : r - 48;
            const uint32_t bh = ((r < 48) ? QKB_OFF : (QKB_OFF + QKB_SZ)) + swz128r(rr, gl);
            *reinterpret_cast<uint4*>(smc + bh) = *reinterpret_cast<uint4*>(h);
        }
    }
    __syncthreads();

    // ---- QK via fp16 HMMA: attn[48][48] = Q . K^T, 6 warps ----
    if (wid < 6) {
        const int wm = (wid >> 1) * 16;
        const int wn = (wid & 1) * 24;
        float acc[3][4];
#pragma unroll
        for (int j = 0; j < 3; j++)
#pragma unroll
            for (int k = 0; k < 4; k++) acc[j][k] = 0.f;

        const int a_r  = wm + (lane & 7) + ((lane >> 3) & 1) * 8;
        const int a_cb = lane >> 4;
        const int b_r  = wn + (lane & 7) + ((lane >> 4) & 1) * 8;
        const int b_cb = (lane >> 3) & 1;
        const int b2_r = wn + 16 + (lane & 7);

#pragma unroll
        for (int k16 = 0; k16 < 4; k16++) {
            uint32_t af[4], b4[4], b2[2];
            ldmx4(af, qh_b + swz128r(a_r, k16 * 2 + a_cb));
            ldmx4(b4, kh_b + swz128r(b_r, k16 * 2 + b_cb));
            ldmx2(b2, kh_b + swz128r(b2_r, k16 * 2 + b_cb));
            mma16816h(acc[0], af, b4[0], b4[1]);
            mma16816h(acc[1], af, b4[2], b4[3]);
            mma16816h(acc[2], af, b2[0], b2[1]);
        }
        const int row = wm + (lane >> 2);
        const int colb = wn + (lane & 3) * 2;
#pragma unroll
        for (int j = 0; j < 3; j++) {
            const int col = colb + j * 8;
            *reinterpret_cast<float2*>(&s_attn[row * S_ATTN_STRIDE + col]) =
                make_float2(acc[j][0] * temp, acc[j][1] * temp);
            *reinterpret_cast<float2*>(&s_attn[(row + 8) * S_ATTN_STRIDE + col]) =
                make_float2(acc[j][2] * temp, acc[j][3] * temp);
        }
    }
    __syncthreads();

    // ---- softmax over d ----
    {
        for (int r = wid; r < 48; r += 8) {
            const float v0 = s_attn[r * S_ATTN_STRIDE + lane];
            const float v1 = (lane < 16) ? s_attn[r * S_ATTN_STRIDE + lane + 32] : -1e30f;
            float m = fmaxf(v0, v1);
#pragma unroll
            for (int off = 16; off; off >>= 1) m = fmaxf(m, __shfl_xor_sync(0xffffffffu, m, off));
            const float e0 = __expf(v0 - m);
            const float e1 = (lane < 16) ? __expf(v1 - m) : 0.f;
            float s = e0 + e1;
#pragma unroll
            for (int off = 16; off; off >>= 1) s += __shfl_xor_sync(0xffffffffu, s, off);
            const float inv = 1.f / s;
            s_attn[r * S_ATTN_STRIDE + lane] = e0 * inv;
            if (lane < 16) s_attn[r * S_ATTN_STRIDE + lane + 32] = e1 * inv;
        }
    }
    __syncthreads();

    MBARRIER_WAIT_PARITY(smem_u32(&a_mbar), 0);

    // ---- out[c][n] = sum_d attn[c][d] * v[d][n]; overlays qk region ----
    float* s_out = reinterpret_cast<float*>(smc + QKB_OFF);   // 48 x SQ
    {
        const int ty = tid >> 4, tx = tid & 15;
        float4 a0c = make_float4(0.f, 0.f, 0.f, 0.f);
        float4 a1c = a0c, a2c = a0c;
        const float* ar0 = s_attn + (ty * 3 + 0) * S_ATTN_STRIDE;
        const float* ar1 = s_attn + (ty * 3 + 1) * S_ATTN_STRIDE;
        const float* ar2 = s_attn + (ty * 3 + 2) * S_ATTN_STRIDE;
#pragma unroll 4
        for (int d = 0; d < 48; ++d) {
            const float a0 = ar0[d], a1 = ar1[d], a2 = ar2[d];
            const float4 v = *reinterpret_cast<const float4*>(&s_v[d * SQ + tx * 4]);
            a0c.x += a0 * v.x; a0c.y += a0 * v.y; a0c.z += a0 * v.z; a0c.w += a0 * v.w;
            a1c.x += a1 * v.x; a1c.y += a1 * v.y; a1c.z += a1 * v.z; a1c.w += a1 * v.w;
            a2c.x += a2 * v.x; a2c.y += a2 * v.y; a2c.z += a2 * v.z; a2c.w += a2 * v.w;
        }
        __syncthreads();   // all QK reads of q/k done before overlay
        *reinterpret_cast<float4*>(&s_out[(ty * 3 + 0) * SQ + tx * 4]) = a0c;
        *reinterpret_cast<float4*>(&s_out[(ty * 3 + 1) * SQ + tx * 4]) = a1c;
        *reinterpret_cast<float4*>(&s_out[(ty * 3 + 2) * SQ + tx * 4]) = a2c;
    }
    __syncthreads();

    // ---- write fp16 to [b][hw][384] ----
    for (int e = tid; e < 1536; e += 256) {
        const int c2 = e % 24;
        const int n  = e / 24;
        const int c  = c2 * 2;
        const float va = s_out[c * SQ + n];
        const float vb = s_out[(c + 1) * SQ + n];
        const int yy = n >> 3, xx = n & 7;
        const int hw = ((wy * 8 + yy) << 8) + wx * 8 + xx;
        const size_t off = ((size_t)b * HW + hw) * DIMC + head * CPH + c;
        *reinterpret_cast<__half2*>(&out_h[off]) = __floats2half2_rn(va, vb);
    }
}

// ---------------- launch ----------------------------------------------------
extern "C" void kernel_launch(void* const* d_in, const int* in_sizes, int n_in,
                              void* d_out, int out_size)
{
    const float* x      = (const float*)d_in[0];
    const float* qkv_w  = (const float*)d_in[1];
    const float* dw_w   = (const float*)d_in[2];
    const float* temp   = (const float*)d_in[3];
    const float* proj_w = (const float*)d_in[4];
    const float* proj_b = (const float*)d_in[5];
    float* out = (float*)d_out;

    float *qkv_buf, *win_buf;
    __half *xt_h, *at_h, *wq_h, *wp_h;
    cudaGetSymbolAddress((void**)&qkv_buf, g_qkv);
    cudaGetSymbolAddress((void**)&win_buf, g_win);
    cudaGetSymbolAddress((void**)&xt_h, g_xt_h);
    cudaGetSymbolAddress((void**)&at_h, g_at_h);
    cudaGetSymbolAddress((void**)&wq_h, g_wq_h);
    cudaGetSymbolAddress((void**)&wp_h, g_wp_h);

    cudaFuncSetAttribute(attn_kernel, cudaFuncAttributeMaxDynamicSharedMemorySize, A_SMEM_BYTES);
    cudaFuncSetAttribute(hmma_gemm_f16<0>, cudaFuncAttributeMaxDynamicSharedMemorySize, HG1_SMEM);
    cudaFuncSetAttribute(hmma_gemm_f16<1>, cudaFuncAttributeMaxDynamicSharedMemorySize, HG1_SMEM);

    // weight prep
    conv_w_h<<<(QKV_M * DIMC + 255) / 256, 256>>>(qkv_w, wq_h, QKV_M * DIMC);
    conv_w_h<<<(DIMC * DIMC + 255) / 256, 256>>>(proj_w, wp_h, DIMC * DIMC);

    // x -> transposed fp16 [b][hw][384]
    transpose_h<<<dim3(HW / 32, DIMC / 32, BATCH), 256>>>(x, xt_h, DIMC, HW);

    // qkv = W_qkv . x   (fp16) -> g_qkv f32
    hmma_gemm_f16<0><<<dim3(QKV_M / 128, HW / 128, BATCH), 256, HG1_SMEM>>>(
        wq_h, xt_h, qkv_buf, QKV_M, HW, DIMC, nullptr);

    // depthwise 3x3 -> window-major layout
    dwconv_kernel<<<dim3(64, HEADS, BATCH), 256>>>(qkv_buf, dw_w, win_buf);

    // window channel attention -> fp16 [b][hw][384]
    attn_kernel<<<dim3(1024, HEADS, BATCH), 256, A_SMEM_BYTES>>>(
        win_buf, temp, at_h);

    // out = W_proj . att + b  (fp16)
    hmma_gemm_f16<1><<<dim3(DIMC / 128, HW / 128, BATCH), 256, HG1_SMEM>>>(
        wp_h, at_h, out, DIMC, HW, DIMC, proj_b);
}

// round 17
// speedup vs baseline: 1.8054x; 1.1145x over previous
#include <cuda_runtime.h>
#include <cuda_fp16.h>
#include <cstdint>
#include <math.h>

// Problem constants
#define DIMC   384
#define HEADS  8
#define CPH    48
#define HH     256
#define WW     256
#define HW     65536
#define BATCH  2
#define QKV_M  1152        // 3*dim

// ---------------- scratch (device globals) ----------------------------------
__device__ __half g_qkv_h[(size_t)BATCH * QKV_M * HW];           // [b][1152][hw] fp16
__device__ __half g_win_h[(size_t)BATCH * HEADS * 1024 * 144 * 64]; // window-major fp16
__device__ __half g_xt_h[(size_t)BATCH * HW * DIMC];             // [b][hw][384] fp16
__device__ __half g_at_h[(size_t)BATCH * HW * DIMC];             // attention out fp16
__device__ __half g_wq_h[QKV_M * DIMC];
__device__ __half g_wp_h[DIMC * DIMC];

// ---------------- helpers ----------------------------------------------------
__device__ __forceinline__ uint32_t smem_u32(const void* p) {
    uint32_t a;
    asm("{ .reg .u64 t; cvta.to.shared.u64 t, %1; cvt.u32.u64 %0, t; }" : "=r"(a) : "l"(p));
    return a;
}
#define CP_ASYNC16(saddr, gptr) \
    asm volatile("cp.async.cg.shared.global [%0], [%1], 16;" :: "r"(saddr), "l"(gptr))
#define CP_COMMIT() asm volatile("cp.async.commit_group;" ::: "memory")
#define CP_WAIT0()  asm volatile("cp.async.wait_group 0;" ::: "memory")
#define CP_WAIT1()  asm volatile("cp.async.wait_group 1;" ::: "memory")

#define MBARRIER_INIT(addr, cnt) \
    asm volatile("mbarrier.init.shared.b64 [%0], %1;" :: "r"((uint32_t)(addr)), "r"((uint32_t)(cnt)) : "memory")
#define MBARRIER_EXPECT_TX(addr, bytes) \
    asm volatile("mbarrier.arrive.expect_tx.shared.b64 _, [%0], %1;" :: "r"((uint32_t)(addr)), "r"((uint32_t)(bytes)) : "memory")
#define MBARRIER_WAIT_PARITY(mbar_addr, parity) do { \
    uint32_t _mbar = (uint32_t)(mbar_addr); \
    uint32_t _par = (uint32_t)(parity); \
    uint32_t _done; \
    asm volatile( \
        "{\n\t.reg .pred p;\n\t" \
        "mbarrier.try_wait.parity.shared.b64 p, [%1], %2;\n\t" \
        "selp.b32 %0, 1, 0, p;\n\t}" \
        : "=r"(_done) : "r"(_mbar), "r"(_par) : "memory"); \
    if (!_done) { \
        asm volatile( \
            "{\n\t.reg .pred P1;\n\t" \
            "WL_%=:\n\t" \
            "mbarrier.try_wait.parity.shared.b64 P1, [%0], %1;\n\t" \
            "@P1 bra.uni WD_%=;\n\t" \
            "bra.uni WL_%=;\n\t" \
            "WD_%=:\n\t}" \
            :: "r"(_mbar), "r"(_par) : "memory"); \
    } \
} while (0)
#define BULK_CPY(dst_smem, gsrc, bytes, mbar) \
    asm volatile("cp.async.bulk.shared::cta.global.mbarrier::complete_tx::bytes [%0], [%1], %2, [%3];" \
                 :: "r"((uint32_t)(dst_smem)), "l"(gsrc), "r"((uint32_t)(bytes)), "r"((uint32_t)(mbar)) : "memory")
#define FENCE_PROXY_ASYNC() asm volatile("fence.proxy.async.shared::cta;" ::: "memory")

__device__ __forceinline__ void ldmx4(uint32_t* d, uint32_t addr) {
    asm volatile("ldmatrix.sync.aligned.m8n8.x4.shared.b16 {%0,%1,%2,%3}, [%4];"
                 : "=r"(d[0]), "=r"(d[1]), "=r"(d[2]), "=r"(d[3]) : "r"(addr));
}
__device__ __forceinline__ void ldmx2(uint32_t* d, uint32_t addr) {
    asm volatile("ldmatrix.sync.aligned.m8n8.x2.shared.b16 {%0,%1}, [%2];"
                 : "=r"(d[0]), "=r"(d[1]) : "r"(addr));
}
__device__ __forceinline__ void mma16816h(float* c, const uint32_t* a, uint32_t b0, uint32_t b1) {
    asm volatile("mma.sync.aligned.m16n8k16.row.col.f32.f16.f16.f32 "
                 "{%0,%1,%2,%3}, {%4,%5,%6,%7}, {%8,%9}, {%0,%1,%2,%3};"
                 : "+f"(c[0]), "+f"(c[1]), "+f"(c[2]), "+f"(c[3])
                 : "r"(a[0]), "r"(a[1]), "r"(a[2]), "r"(a[3]), "r"(b0), "r"(b1));
}
__device__ __forceinline__ uint32_t swz(int r, int cb) {          // 64B rows (GEMM tiles)
    return (uint32_t)(r * 64 + ((cb ^ ((r >> 1) & 3)) << 4));
}
__device__ __forceinline__ uint32_t swz128r(int r, int cb) {      // 128B rows (attn fp16)
    return (uint32_t)(r * 128 + ((cb ^ (r & 7)) << 4));
}

// ---------------- transpose to fp16 ------------------------------------------
__global__ __launch_bounds__(256) void transpose_h(
    const float* __restrict__ in, __half* __restrict__ outp, int C, int N)
{
    __shared__ float t[32][33];
    const int n0 = blockIdx.x * 32, c0 = blockIdx.y * 32;
    const size_t base = (size_t)blockIdx.z * C * N;
    const int tx = threadIdx.x & 31, ty = threadIdx.x >> 5;
#pragma unroll
    for (int i = 0; i < 4; i++) {
        const int c = ty + i * 8;
        t[c][tx] = in[base + (size_t)(c0 + c) * N + n0 + tx];
    }
    __syncthreads();
#pragma unroll
    for (int i = 0; i < 4; i++) {
        const int n = ty + i * 8;
        outp[base + (size_t)(n0 + n) * C + c0 + tx] = __float2half(t[tx][n]);
    }
}

__global__ void conv_w_h(const float* __restrict__ w, __half* __restrict__ outp, int n)
{
    const int i = blockIdx.x * 256 + threadIdx.x;
    if (i < n) outp[i] = __float2half(w[i]);
}

// ---------------- fp16 single-pass GEMM: C = A . B^T (+bias) ----------------
// A [M][K] fp16, B per-batch [N][K] fp16. C: fp16 (GEMM1) or f32+bias (GEMM2).
#define HG1_SMEM 49152

template <int WITH_BIAS, typename TOUT>
__global__ __launch_bounds__(256) void hmma_gemm_f16(
    const __half* __restrict__ Ag, const __half* __restrict__ Bg,
    TOUT* __restrict__ Cg, int M, int N, int K, const float* __restrict__ bias)
{
    extern __shared__ char smem[];
    const uint32_t sb = smem_u32(smem);
    const int tid = threadIdx.x;
    const int wid = tid >> 5, lane = tid & 31;
    const int bM = blockIdx.x * 128;
    const int bN = blockIdx.y * 128;
    const size_t bb = (size_t)blockIdx.z * (size_t)N * K;
    TOUT* Cp = Cg + (size_t)blockIdx.z * (size_t)M * N;

    const __half* A = Ag + (size_t)bM * K;
    const __half* B = Bg + bb + (size_t)bN * K;

    const int cb = tid & 3;
    const int r0 = tid >> 2;
    const int nst = K / 32;

#pragma unroll
    for (int ps = 0; ps < 2; ps++) {
        const uint32_t st = sb + ps * 16384;
        const int kk = ps * 32 + cb * 8;
#pragma unroll
        for (int i = 0; i < 2; i++) {
            const int r = r0 + i * 64;
            const uint32_t so = swz(r, cb);
            CP_ASYNC16(st + so,        A + (size_t)r * K + kk);
            CP_ASYNC16(st + 8192 + so, B + (size_t)r * K + kk);
        }
        CP_COMMIT();
    }

    float acc[4][4][4];
#pragma unroll
    for (int i = 0; i < 4; i++)
#pragma unroll
        for (int j = 0; j < 4; j++)
#pragma unroll
            for (int k = 0; k < 4; k++) acc[i][j][k] = 0.f;

    const int wm = (wid >> 2) * 64;
    const int wn = (wid & 3) * 32;
    const int a_rbase = wm + ((lane >> 3) & 1) * 8 + (lane & 7);
    const int a_cbad  = lane >> 4;
    const int b_rbase = wn + ((lane >> 4) & 1) * 8 + (lane & 7);
    const int b_cbad  = (lane >> 3) & 1;

    int sidx = 0;
    for (int s = 0; s < nst; s++) {
        if (s + 1 < nst) CP_WAIT1(); else CP_WAIT0();
        __syncthreads();

        if (s + 2 < nst) {
            int fi = sidx + 2; if (fi >= 3) fi -= 3;
            const uint32_t st = sb + fi * 16384;
            const int kk = (s + 2) * 32 + cb * 8;
#pragma unroll
            for (int i = 0; i < 2; i++) {
                const int r = r0 + i * 64;
                const uint32_t so = swz(r, cb);
                CP_ASYNC16(st + so,        A + (size_t)r * K + kk);
                CP_ASYNC16(st + 8192 + so, B + (size_t)r * K + kk);
            }
            CP_COMMIT();
        }

        const uint32_t st = sb + sidx * 16384;
#pragma unroll
        for (int k16 = 0; k16 < 2; k16++) {
            uint32_t bf[2][4];
#pragma unroll
            for (int nh = 0; nh < 2; nh++)
                ldmx4(bf[nh], st + 8192 + swz(b_rbase + nh * 16, k16 * 2 + b_cbad));
#pragma unroll
            for (int mh = 0; mh < 4; mh++) {
                uint32_t af[4];
                ldmx4(af, st + swz(a_rbase + mh * 16, k16 * 2 + a_cbad));
#pragma unroll
                for (int nb = 0; nb < 4; nb++) {
                    const uint32_t* f = &bf[nb >> 1][(nb & 1) * 2];
                    mma16816h(acc[mh][nb], af, f[0], f[1]);
                }
            }
        }
        if (++sidx == 3) sidx = 0;
    }
    __syncthreads();

    const int row0 = bM + wm + (lane >> 2);
    const int col0 = bN + wn + (lane & 3) * 2;
#pragma unroll
    for (int mh = 0; mh < 4; mh++) {
#pragma unroll
        for (int p = 0; p < 2; p++) {
            const int row = row0 + mh * 16 + p * 8;
            const float bi = WITH_BIAS ? __ldg(&bias[row]) : 0.f;
#pragma unroll
            for (int nb = 0; nb < 4; nb++) {
                const float vx = acc[mh][nb][p * 2 + 0] + bi;
                const float vy = acc[mh][nb][p * 2 + 1] + bi;
                if constexpr (sizeof(TOUT) == 2) {
                    *reinterpret_cast<__half2*>(&Cp[(size_t)row * N + col0 + nb * 8]) =
                        __floats2half2_rn(vx, vy);
                } else {
                    *reinterpret_cast<float2*>(&Cp[(size_t)row * N + col0 + nb * 8]) =
                        make_float2(vx, vy);
                }
            }
        }
    }
}

// ---------------- dwconv 3x3 (fp16 in/out) -> window-major -------------------
// halo buffer: 34 rows x 48 halves; window base element = x0-7 (8-aligned).
#define HSTRH 48

__global__ __launch_bounds__(256) void dwconv_kernel(
    const __half* __restrict__ qkv1,    // [b][1152][hw] fp16
    const float* __restrict__ dww,      // [1152][9]
    __half* __restrict__ gwin)          // window-major fp16
{
    __shared__ __align__(16) __half h6[6][34 * HSTRH];
    __shared__ float s_dww[144 * 9];
    __shared__ __align__(8) uint64_t mbar[3];

    const int tid  = threadIdx.x;
    const int tile = blockIdx.x;           // 0..63
    const int head = blockIdx.y;
    const int b    = blockIdx.z;
    const int tyb = tile >> 3, txb = tile & 7;
    const int y0 = tyb * 32 - 1, x0 = txb * 32 - 1;
    const int base2 = x0 - 7;              // 32*txb - 8, 8-aligned

    const int src_start = base2 < 0 ? 0 : base2;
    const int src_end   = (base2 + 48 > 256) ? 256 : (base2 + 48);
    const int dst_elems = src_start - base2;           // 0 or 8
    const uint32_t rowbytes = (uint32_t)(src_end - src_start) * 2;  // 80 or 96
    const int r_lo = (y0 < 0) ? 1 : 0;
    const int r_hi = (y0 + 33 > 255) ? 32 : 33;
    const uint32_t expect2 = 2u * (uint32_t)(r_hi - r_lo + 1) * rowbytes;

    for (int e = tid; e < 144 * 9; e += 256) {
        const int l = e / 9, kk = e - l * 9;
        const int z = l / 48, cl = l - z * 48;
        s_dww[e] = dww[(size_t)(z * DIMC + head * CPH + cl) * 9 + kk];
    }
    for (int e = tid; e < 6 * 34 * HSTRH / 2; e += 256)
        reinterpret_cast<uint32_t*>(&h6[0][0])[e] = 0u;
    if (tid < 3) MBARRIER_INIT(smem_u32(&mbar[tid]), 1);
    __syncthreads();
    FENCE_PROXY_ASYNC();

    const size_t bbase = (size_t)b * QKV_M * HW;
    const int wid = tid >> 5, lane = tid & 31;

    auto issue = [&](int s) {
        const int slot = s % 3;
        const uint32_t mb = smem_u32(&mbar[slot]);
        if (lane == 0) MBARRIER_EXPECT_TX(mb, expect2);
        for (int i = lane; i < 68; i += 32) {
            const int sub = i / 34;
            const int r = i - sub * 34;
            if (r < r_lo || r > r_hi) continue;
            const int ch = 2 * s + sub;
            const int gc = (ch / 48) * DIMC + head * CPH + (ch % 48);
            const __half* srcc = qkv1 + bbase + (size_t)gc * HW;
            BULK_CPY(smem_u32(&h6[slot * 2 + sub][0]) + (uint32_t)(r * HSTRH + dst_elems) * 2,
                     srcc + (size_t)(y0 + r) * 256 + src_start, rowbytes, mb);
        }
    };
    if (wid == 0) { issue(0); issue(1); }

    // coalesced output: 16 threads per window, contiguous 128B runs (fp16)
    const int wl = tid >> 4;
    const int e0 = (tid & 15) * 4;
    const int wy_l = wl >> 2, wx_l = wl & 3;
    const int orow = wy_l * 8 + (e0 >> 3);
    const int xq   = wx_l * 8 + (e0 & 7);
    const int win = (tyb * 4 + wy_l) * 32 + txb * 4 + wx_l;
    __half* wbase = gwin + (((size_t)(b * HEADS + head) * 1024 + win) * 144) * 64 + e0;

#pragma unroll 1
    for (int s = 0; s < 72; s++) {
        if (wid == 0 && s + 2 < 72) issue(s + 2);
        MBARRIER_WAIT_PARITY(smem_u32(&mbar[s % 3]), (s / 3) & 1);

#pragma unroll
        for (int sub = 0; sub < 2; sub++) {
            const int ch = 2 * s + sub;
            const __half* hb = h6[(s % 3) * 2 + sub] + orow * HSTRH + xq + 7;
            const float* wp = s_dww + ch * 9;
            float w[9];
#pragma unroll
            for (int i = 0; i < 9; i++) w[i] = wp[i];
            float a[3][6];
#pragma unroll
            for (int dy = 0; dy < 3; dy++)
#pragma unroll
                for (int c = 0; c < 6; c++) a[dy][c] = __half2float(hb[dy * HSTRH + c]);
            __half2 o01 = __floats2half2_rn(
                a[0][0]*w[0] + a[0][1]*w[1] + a[0][2]*w[2]
              + a[1][0]*w[3] + a[1][1]*w[4] + a[1][2]*w[5]
              + a[2][0]*w[6] + a[2][1]*w[7] + a[2][2]*w[8],
                a[0][1]*w[0] + a[0][2]*w[1] + a[0][3]*w[2]
              + a[1][1]*w[3] + a[1][2]*w[4] + a[1][3]*w[5]
              + a[2][1]*w[6] + a[2][2]*w[7] + a[2][3]*w[8]);
            __half2 o23 = __floats2half2_rn(
                a[0][2]*w[0] + a[0][3]*w[1] + a[0][4]*w[2]
              + a[1][2]*w[3] + a[1][3]*w[4] + a[1][4]*w[5]
              + a[2][2]*w[6] + a[2][3]*w[7] + a[2][4]*w[8],
                a[0][3]*w[0] + a[0][4]*w[1] + a[0][5]*w[2]
              + a[1][3]*w[3] + a[1][4]*w[4] + a[1][5]*w[5]
              + a[2][3]*w[6] + a[2][4]*w[7] + a[2][5]*w[8]);
            uint2 pk;
            pk.x = *reinterpret_cast<uint32_t*>(&o01);
            pk.y = *reinterpret_cast<uint32_t*>(&o23);
            *reinterpret_cast<uint2*>(wbase + (size_t)ch * 64) = pk;
        }
        __syncthreads();
    }
}

// ---------------- window channel-attention (fp16 everywhere) -----------------
// smem: s_v fp16 [48][72] @0 (6912B) | s_attn f32 [48][50] @6912 (9600B)
//       | q fp16 @16512 (6144) | k fp16 @22656 (6144) | s_out f32 overlays @16512
#define SVH 72
#define S_ATTN_STRIDE 50
#define AT_OFFB  6912                          // bytes
#define QKB_OFF  16512                         // bytes
#define QKB_SZ   6144
#define SQ 68
#define A_SMEM_BYTES (QKB_OFF + 13056)         // 29568

__global__ __launch_bounds__(256) void attn_kernel(
    const __half* __restrict__ gwin,         // [(b*8+head)*1024+win][144][64] fp16
    const float* __restrict__ temperature,
    __half* __restrict__ out_h)              // [b][hw][384] fp16
{
    extern __shared__ char smc[];
    __half* s_v   = reinterpret_cast<__half*>(smc);            // 48 x SVH
    float* s_attn = reinterpret_cast<float*>(smc + AT_OFFB);   // 48 x 50
    __shared__ __align__(8) uint64_t a_mbar;
    const uint32_t smb = smem_u32(smc);
    const uint32_t qh_b = smb + QKB_OFF;
    const uint32_t kh_b = smb + QKB_OFF + QKB_SZ;

    const int tid  = threadIdx.x;
    const int win  = blockIdx.x;
    const int head = blockIdx.y;
    const int b    = blockIdx.z;
    const int wy = win >> 5, wx = win & 31;
    const int wid = tid >> 5, lane = tid & 31;

    if (tid == 0) MBARRIER_INIT(smem_u32(&a_mbar), 1);
    __syncthreads();

    const __half* base = gwin + (((size_t)(b * HEADS + head) * 1024 + win) * 144) * 64;

    // ---- bulk-copy v (rows 96..143), 128B per row ----
    if (tid < 32) {
        const uint32_t mb = smem_u32(&a_mbar);
        if (tid == 0) MBARRIER_EXPECT_TX(mb, 48 * 128);
        for (int r = tid; r < 48; r += 32)
            BULK_CPY(smb + (uint32_t)(r * SVH) * 2, base + (size_t)(96 + r) * 64, 128, mb);
    }

    const float temp = __ldg(&temperature[head]);

    // ---- L2 normalize q,k from GLOBAL fp16; emit fp16 swizzled ----
    {
        const int grp = tid >> 3;
        const int gl  = tid & 7;
#pragma unroll
        for (int it = 0; it < 3; it++) {
            const int r = grp + it * 32;     // 0..95
            const __half2* gp = reinterpret_cast<const __half2*>(base + (size_t)r * 64 + gl * 8);
            __half2 hv[4];
            *reinterpret_cast<uint4*>(hv) = *reinterpret_cast<const uint4*>(gp);
            float f[8];
#pragma unroll
            for (int p = 0; p < 4; p++) {
                const float2 t2 = __half22float2(hv[p]);
                f[2 * p] = t2.x; f[2 * p + 1] = t2.y;
            }
            float s = 0.f;
#pragma unroll
            for (int p = 0; p < 8; p++) s += f[p] * f[p];
            s += __shfl_xor_sync(0xffffffffu, s, 1);
            s += __shfl_xor_sync(0xffffffffu, s, 2);
            s += __shfl_xor_sync(0xffffffffu, s, 4);
            const float inv = 1.f / fmaxf(sqrtf(s), 1e-12f);
            __half2 h[4];
#pragma unroll
            for (int p = 0; p < 4; p++)
                h[p] = __floats2half2_rn(f[2 * p] * inv, f[2 * p + 1] * inv);
            const int rr = (r < 48) ? r : r - 48;
            const uint32_t bh = ((r < 48) ? QKB_OFF : (QKB_OFF + QKB_SZ)) + swz128r(rr, gl);
            *reinterpret_cast<uint4*>(smc + bh) = *reinterpret_cast<uint4*>(h);
        }
    }
    __syncthreads();

    // ---- QK via fp16 HMMA: attn[48][48] = Q . K^T, 6 warps ----
    if (wid < 6) {
        const int wm = (wid >> 1) * 16;
        const int wn = (wid & 1) * 24;
        float acc[3][4];
#pragma unroll
        for (int j = 0; j < 3; j++)
#pragma unroll
            for (int k = 0; k < 4; k++) acc[j][k] = 0.f;

        const int a_r  = wm + (lane & 7) + ((lane >> 3) & 1) * 8;
        const int a_cb = lane >> 4;
        const int b_r  = wn + (lane & 7) + ((lane >> 4) & 1) * 8;
        const int b_cb = (lane >> 3) & 1;
        const int b2_r = wn + 16 + (lane & 7);

#pragma unroll
        for (int k16 = 0; k16 < 4; k16++) {
            uint32_t af[4], b4[4], b2[2];
            ldmx4(af, qh_b + swz128r(a_r, k16 * 2 + a_cb));
            ldmx4(b4, kh_b + swz128r(b_r, k16 * 2 + b_cb));
            ldmx2(b2, kh_b + swz128r(b2_r, k16 * 2 + b_cb));
            mma16816h(acc[0], af, b4[0], b4[1]);
            mma16816h(acc[1], af, b4[2], b4[3]);
            mma16816h(acc[2], af, b2[0], b2[1]);
        }
        const int row = wm + (lane >> 2);
        const int colb = wn + (lane & 3) * 2;
#pragma unroll
        for (int j = 0; j < 3; j++) {
            const int col = colb + j * 8;
            *reinterpret_cast<float2*>(&s_attn[row * S_ATTN_STRIDE + col]) =
                make_float2(acc[j][0] * temp, acc[j][1] * temp);
            *reinterpret_cast<float2*>(&s_attn[(row + 8) * S_ATTN_STRIDE + col]) =
                make_float2(acc[j][2] * temp, acc[j][3] * temp);
        }
    }
    __syncthreads();

    // ---- softmax over d ----
    {
        for (int r = wid; r < 48; r += 8) {
            const float v0 = s_attn[r * S_ATTN_STRIDE + lane];
            const float v1 = (lane < 16) ? s_attn[r * S_ATTN_STRIDE + lane + 32] : -1e30f;
            float m = fmaxf(v0, v1);
#pragma unroll
            for (int off = 16; off; off >>= 1) m = fmaxf(m, __shfl_xor_sync(0xffffffffu, m, off));
            const float e0 = __expf(v0 - m);
            const float e1 = (lane < 16) ? __expf(v1 - m) : 0.f;
            float s = e0 + e1;
#pragma unroll
            for (int off = 16; off; off >>= 1) s += __shfl_xor_sync(0xffffffffu, s, off);
            const float inv = 1.f / s;
            s_attn[r * S_ATTN_STRIDE + lane] = e0 * inv;
            if (lane < 16) s_attn[r * S_ATTN_STRIDE + lane + 32] = e1 * inv;
        }
    }
    __syncthreads();

    MBARRIER_WAIT_PARITY(smem_u32(&a_mbar), 0);

    // ---- out[c][n] = sum_d attn[c][d] * v[d][n]; overlays qk region ----
    float* s_out = reinterpret_cast<float*>(smc + QKB_OFF);   // 48 x SQ f32
    {
        const int ty = tid >> 4, tx = tid & 15;
        float4 a0c = make_float4(0.f, 0.f, 0.f, 0.f);
        float4 a1c = a0c, a2c = a0c;
        const float* ar0 = s_attn + (ty * 3 + 0) * S_ATTN_STRIDE;
        const float* ar1 = s_attn + (ty * 3 + 1) * S_ATTN_STRIDE;
        const float* ar2 = s_attn + (ty * 3 + 2) * S_ATTN_STRIDE;
#pragma unroll 4
        for (int d = 0; d < 48; ++d) {
            const float a0 = ar0[d], a1 = ar1[d], a2 = ar2[d];
            __half2 vh[2];
            *reinterpret_cast<uint2*>(vh) =
                *reinterpret_cast<const uint2*>(&s_v[d * SVH + tx * 4]);
            const float2 vA = __half22float2(vh[0]);
            const float2 vB = __half22float2(vh[1]);
            a0c.x += a0 * vA.x; a0c.y += a0 * vA.y; a0c.z += a0 * vB.x; a0c.w += a0 * vB.y;
            a1c.x += a1 * vA.x; a1c.y += a1 * vA.y; a1c.z += a1 * vB.x; a1c.w += a1 * vB.y;
            a2c.x += a2 * vA.x; a2c.y += a2 * vA.y; a2c.z += a2 * vB.x; a2c.w += a2 * vB.y;
        }
        __syncthreads();   // all QK reads of q/k done before overlay
        *reinterpret_cast<float4*>(&s_out[(ty * 3 + 0) * SQ + tx * 4]) = a0c;
        *reinterpret_cast<float4*>(&s_out[(ty * 3 + 1) * SQ + tx * 4]) = a1c;
        *reinterpret_cast<float4*>(&s_out[(ty * 3 + 2) * SQ + tx * 4]) = a2c;
    }
    __syncthreads();

    // ---- write fp16 to [b][hw][384] ----
    for (int e = tid; e < 1536; e += 256) {
        const int c2 = e % 24;
        const int n  = e / 24;
        const int c  = c2 * 2;
        const float va = s_out[c * SQ + n];
        const float vb = s_out[(c + 1) * SQ + n];
        const int yy = n >> 3, xx = n & 7;
        const int hw = ((wy * 8 + yy) << 8) + wx * 8 + xx;
        const size_t off = ((size_t)b * HW + hw) * DIMC + head * CPH + c;
        *reinterpret_cast<__half2*>(&out_h[off]) = __floats2half2_rn(va, vb);
    }
}

// ---------------- launch ----------------------------------------------------
extern "C" void kernel_launch(void* const* d_in, const int* in_sizes, int n_in,
                              void* d_out, int out_size)
{
    const float* x      = (const float*)d_in[0];
    const float* qkv_w  = (const float*)d_in[1];
    const float* dw_w   = (const float*)d_in[2];
    const float* temp   = (const float*)d_in[3];
    const float* proj_w = (const float*)d_in[4];
    const float* proj_b = (const float*)d_in[5];
    float* out = (float*)d_out;

    __half *qkv_h, *win_h, *xt_h, *at_h, *wq_h, *wp_h;
    cudaGetSymbolAddress((void**)&qkv_h, g_qkv_h);
    cudaGetSymbolAddress((void**)&win_h, g_win_h);
    cudaGetSymbolAddress((void**)&xt_h, g_xt_h);
    cudaGetSymbolAddress((void**)&at_h, g_at_h);
    cudaGetSymbolAddress((void**)&wq_h, g_wq_h);
    cudaGetSymbolAddress((void**)&wp_h, g_wp_h);

    cudaFuncSetAttribute(attn_kernel, cudaFuncAttributeMaxDynamicSharedMemorySize, A_SMEM_BYTES);
    cudaFuncSetAttribute(hmma_gemm_f16<0, __half>, cudaFuncAttributeMaxDynamicSharedMemorySize, HG1_SMEM);
    cudaFuncSetAttribute(hmma_gemm_f16<1, float>, cudaFuncAttributeMaxDynamicSharedMemorySize, HG1_SMEM);

    // weight prep
    conv_w_h<<<(QKV_M * DIMC + 255) / 256, 256>>>(qkv_w, wq_h, QKV_M * DIMC);
    conv_w_h<<<(DIMC * DIMC + 255) / 256, 256>>>(proj_w, wp_h, DIMC * DIMC);

    // x -> transposed fp16 [b][hw][384]
    transpose_h<<<dim3(HW / 32, DIMC / 32, BATCH), 256>>>(x, xt_h, DIMC, HW);

    // qkv = W_qkv . x   (fp16) -> fp16
    hmma_gemm_f16<0, __half><<<dim3(QKV_M / 128, HW / 128, BATCH), 256, HG1_SMEM>>>(
        wq_h, xt_h, qkv_h, QKV_M, HW, DIMC, nullptr);

    // depthwise 3x3 -> window-major fp16
    dwconv_kernel<<<dim3(64, HEADS, BATCH), 256>>>(qkv_h, dw_w, win_h);

    // window channel attention -> fp16 [b][hw][384]
    attn_kernel<<<dim3(1024, HEADS, BATCH), 256, A_SMEM_BYTES>>>(
        win_h, temp, at_h);

    // out = W_proj . att + b  (fp16 -> f32)
    hmma_gemm_f16<1, float><<<dim3(DIMC / 128, HW / 128, BATCH), 256, HG1_SMEM>>>(
        wp_h, at_h, out, DIMC, HW, DIMC, proj_b);
}